// round 5
// baseline (speedup 1.0000x reference)
#include <cuda_runtime.h>
#include <cuda_fp16.h>
#include <math.h>
#include <cstdint>

// ---------------------------------------------------------------------------
// MEGA forward, mma.sync fp16 GEMMs, 256x128 CTA tiles / 64x64 warp tiles.
// L=2048 B=8 D=1024 Z=128 H=2048 N=16
// ---------------------------------------------------------------------------

#define LSEQ   2048
#define BATCH  8
#define DDIM   1024
#define ZDIM   128
#define HDIM   2048
#define NEMA   16
#define MAXPOS 2048
#define DOUT   (ZDIM + HDIM + 2 * DDIM)   // 4224
#define NCH    8
#define CHL    (LSEQ / NCH)               // 256

// ------------------------- scratch (device globals) ------------------------
__device__ float  g_xn  [LSEQ * BATCH * DDIM];
__device__ float  g_u   [LSEQ * BATCH * DDIM];
__device__ float  g_hx  [LSEQ * BATCH * DDIM];
__device__ float  g_r   [(size_t)BATCH * LSEQ * HDIM];
__device__ __half xn16  [LSEQ * BATCH * DDIM];
__device__ __half mx16  [LSEQ * BATCH * DDIM];
__device__ __half v16   [(size_t)BATCH * LSEQ * HDIM];
__device__ __half vT16  [(size_t)BATCH * HDIM * LSEQ];
__device__ __half h16   [(size_t)BATCH * LSEQ * HDIM];
__device__ __half q16   [BATCH * LSEQ * ZDIM];
__device__ __half k16   [BATCH * LSEQ * ZDIM];
__device__ __half attn16[(size_t)BATCH * LSEQ * LSEQ];
__device__ __half w_v16 [HDIM * DDIM];
__device__ __half w_mx16[(size_t)DOUT * DDIM];
__device__ __half w_h16 [DDIM * HDIM];
__device__ float  g_wn  [DDIM * NEMA];
__device__ float  g_qn  [DDIM * NEMA];
__device__ float  g_qp  [DDIM * NEMA];
__device__ float  g_send [BATCH * NCH * DDIM * NEMA];
__device__ float  g_carry[BATCH * NCH * DDIM * NEMA];

// ------------------------------- ptx helpers --------------------------------
__device__ __forceinline__ uint32_t smem_u32(const void* p) {
    uint32_t a;
    asm("{ .reg .u64 t; cvta.to.shared.u64 t, %1; cvt.u32.u64 %0, t; }" : "=r"(a) : "l"(p));
    return a;
}
#define CP16(dst, src) \
    asm volatile("cp.async.cg.shared.global [%0], [%1], 16;" :: "r"(dst), "l"(src))
#define CP_COMMIT() asm volatile("cp.async.commit_group;" ::: "memory")
#define CP_WAIT(n)  asm volatile("cp.async.wait_group %0;" :: "n"(n) : "memory")

__device__ __forceinline__ void ldsm4(uint32_t& r0, uint32_t& r1, uint32_t& r2,
                                      uint32_t& r3, uint32_t addr) {
    asm volatile("ldmatrix.sync.aligned.m8n8.x4.shared.b16 {%0,%1,%2,%3}, [%4];"
                 : "=r"(r0), "=r"(r1), "=r"(r2), "=r"(r3) : "r"(addr));
}
__device__ __forceinline__ void mma16816(float* d, const uint32_t* a,
                                         uint32_t b0, uint32_t b1) {
    asm volatile(
        "mma.sync.aligned.m16n8k16.row.col.f32.f16.f16.f32 "
        "{%0,%1,%2,%3}, {%4,%5,%6,%7}, {%8,%9}, {%0,%1,%2,%3};"
        : "+f"(d[0]), "+f"(d[1]), "+f"(d[2]), "+f"(d[3])
        : "r"(a[0]), "r"(a[1]), "r"(a[2]), "r"(a[3]), "r"(b0), "r"(b1));
}
__device__ __forceinline__ uint32_t swz(int row, int c) {
    return (uint32_t)(row * 64 + ((c ^ ((row >> 1) & 3)) << 4));
}

// ------------------------------- math helpers --------------------------------
__device__ __forceinline__ float sigmoidf_(float x) { return 1.f / (1.f + __expf(-x)); }
__device__ __forceinline__ float siluf_(float x)    { return x / (1.f + __expf(-x)); }
__device__ __forceinline__ float laplacef_(float x) {
    const float mu  = 0.707107f;
    const float inv = 1.0f / (0.282095f * 1.41421356237f);
    return 0.5f * (1.0f + erff((x - mu) * inv));
}

// ------------------------------ layernorm ------------------------------------
__global__ void ln_kernel(const float* __restrict__ x,
                          const float* __restrict__ w,
                          const float* __restrict__ bb) {
    int row = blockIdx.x;
    const float4* xr = (const float4*)(x + (size_t)row * DDIM);
    float4 v = xr[threadIdx.x];
    float s  = v.x + v.y + v.z + v.w;
    float s2 = v.x * v.x + v.y * v.y + v.z * v.z + v.w * v.w;
    #pragma unroll
    for (int o = 16; o; o >>= 1) {
        s  += __shfl_xor_sync(0xffffffffu, s, o);
        s2 += __shfl_xor_sync(0xffffffffu, s2, o);
    }
    __shared__ float sm[8], sm2[8];
    int wid = threadIdx.x >> 5, lid = threadIdx.x & 31;
    if (!lid) { sm[wid] = s; sm2[wid] = s2; }
    __syncthreads();
    if (threadIdx.x < 32) {
        s  = (threadIdx.x < 8) ? sm [threadIdx.x] : 0.f;
        s2 = (threadIdx.x < 8) ? sm2[threadIdx.x] : 0.f;
        #pragma unroll
        for (int o = 4; o; o >>= 1) {
            s  += __shfl_xor_sync(0xffffffffu, s, o);
            s2 += __shfl_xor_sync(0xffffffffu, s2, o);
        }
        if (!threadIdx.x) { sm[0] = s; sm2[0] = s2; }
    }
    __syncthreads();
    float mean = sm[0] * (1.f / DDIM);
    float var  = sm2[0] * (1.f / DDIM) - mean * mean;
    float rstd = rsqrtf(var + 1e-5f);
    int c = threadIdx.x * 4;
    float4 o4;
    o4.x = (v.x - mean) * rstd * w[c + 0] + bb[c + 0];
    o4.y = (v.y - mean) * rstd * w[c + 1] + bb[c + 1];
    o4.z = (v.z - mean) * rstd * w[c + 2] + bb[c + 2];
    o4.w = (v.w - mean) * rstd * w[c + 3] + bb[c + 3];
    size_t o = (size_t)row * DDIM + c;
    ((float4*)(g_xn + (size_t)row * DDIM))[threadIdx.x] = o4;
    *(__half2*)(xn16 + o)     = __floats2half2_rn(o4.x, o4.y);
    *(__half2*)(xn16 + o + 2) = __floats2half2_rn(o4.z, o4.w);
}

// --------------------------- EMA coefficients --------------------------------
__global__ void ema_coef_kernel(const float* __restrict__ delta,
                                const float* __restrict__ alpha,
                                const float* __restrict__ beta,
                                const float* __restrict__ gamma) {
    int i = blockIdx.x * 256 + threadIdx.x;
    float p = sigmoidf_(delta[i]);
    float q = 1.f - p * sigmoidf_(alpha[i]);
    g_qn[i] = q;
    g_wn[i] = p * beta[i] * gamma[i] * 0.25f;
    float qp = q;
    #pragma unroll
    for (int k = 0; k < 8; k++) qp *= qp;   // q^256
    g_qp[i] = qp;
}

// ---------------------------- EMA 3-phase scan --------------------------------
__global__ void ema_scanA() {
    int idx = blockIdx.x * 256 + threadIdx.x;
    int d = idx & (DDIM - 1);
    int t = idx >> 10;
    int b = t & 7, c = t >> 3;
    float q[NEMA], s[NEMA];
    #pragma unroll
    for (int n = 0; n < NEMA; n++) { q[n] = g_qn[d * NEMA + n]; s[n] = 0.f; }
    size_t xi = ((size_t)(c * CHL) * BATCH + b) * DDIM + d;
    for (int l = 0; l < CHL; l++) {
        float xv = g_xn[xi];
        #pragma unroll
        for (int n = 0; n < NEMA; n++) s[n] = q[n] * s[n] + xv;
        xi += (size_t)BATCH * DDIM;
    }
    float* dst = g_send + ((size_t)(b * NCH + c) * DDIM + d) * NEMA;
    #pragma unroll
    for (int n = 0; n < NEMA; n++) dst[n] = s[n];
}

__global__ void ema_scanB() {
    int idx = blockIdx.x * 256 + threadIdx.x;
    int d = idx & (DDIM - 1);
    int b = idx >> 10;
    float carry[NEMA], qp[NEMA];
    #pragma unroll
    for (int n = 0; n < NEMA; n++) { carry[n] = 0.f; qp[n] = g_qp[d * NEMA + n]; }
    for (int c = 0; c < NCH; c++) {
        float* cd = g_carry + ((size_t)(b * NCH + c) * DDIM + d) * NEMA;
        const float* sd = g_send + ((size_t)(b * NCH + c) * DDIM + d) * NEMA;
        #pragma unroll
        for (int n = 0; n < NEMA; n++) {
            cd[n] = carry[n];
            carry[n] = qp[n] * carry[n] + sd[n];
        }
    }
}

__global__ void ema_scanC(const float* __restrict__ omega) {
    int idx = blockIdx.x * 256 + threadIdx.x;
    int d = idx & (DDIM - 1);
    int t = idx >> 10;
    int b = t & 7, c = t >> 3;
    float q[NEMA], w[NEMA], s[NEMA];
    const float* cd = g_carry + ((size_t)(b * NCH + c) * DDIM + d) * NEMA;
    #pragma unroll
    for (int n = 0; n < NEMA; n++) {
        q[n] = g_qn[d * NEMA + n];
        w[n] = g_wn[d * NEMA + n];
        s[n] = cd[n];
    }
    float om = omega[d];
    size_t xi = ((size_t)(c * CHL) * BATCH + b) * DDIM + d;
    for (int l = 0; l < CHL; l++) {
        float xv = g_xn[xi];
        float a0 = 0.f, a1 = 0.f;
        #pragma unroll
        for (int n = 0; n < NEMA; n += 2) {
            s[n]     = q[n]     * s[n]     + xv;  a0 += w[n]     * s[n];
            s[n + 1] = q[n + 1] * s[n + 1] + xv;  a1 += w[n + 1] * s[n + 1];
        }
        mx16[xi] = __float2half(siluf_(a0 + a1 + om * xv));
        xi += (size_t)BATCH * DDIM;
    }
}

// ------------------------------ transposes -----------------------------------
template <int WHICH>
__global__ void transpose_w(const float* __restrict__ in, int R, int C) {
    __shared__ float t[32][33];
    __half* op = (WHICH == 0) ? w_v16 : (WHICH == 1) ? w_mx16 : w_h16;
    int c0 = blockIdx.x * 32, r0 = blockIdx.y * 32;
    int tx = threadIdx.x, ty = threadIdx.y;
    #pragma unroll
    for (int k = 0; k < 4; k++)
        t[ty + 8 * k][tx] = in[(size_t)(r0 + ty + 8 * k) * C + c0 + tx];
    __syncthreads();
    #pragma unroll
    for (int k = 0; k < 4; k++)
        op[(size_t)(c0 + ty + 8 * k) * R + r0 + tx] = __float2half(t[tx][ty + 8 * k]);
}

__global__ void transpose_v16() {
    __shared__ __half t[32][36];
    const __half* ip = v16 + (size_t)blockIdx.z * LSEQ * HDIM;
    __half* op = vT16 + (size_t)blockIdx.z * (size_t)HDIM * LSEQ;
    int c0 = blockIdx.x * 32, r0 = blockIdx.y * 32;
    int tx = threadIdx.x, ty = threadIdx.y;
    #pragma unroll
    for (int k = 0; k < 4; k++)
        t[ty + 8 * k][tx] = ip[(size_t)(r0 + ty + 8 * k) * HDIM + c0 + tx];
    __syncthreads();
    #pragma unroll
    for (int k = 0; k < 4; k++)
        op[(size_t)(c0 + ty + 8 * k) * LSEQ + r0 + tx] = t[tx][ty + 8 * k];
}

// --------------------------- fp16 mma.sync GEMM ------------------------------
// 256x128 CTA tile, 8 warps as 4(m) x 2(n), 64x64 warp tile, K-chunk 32.
// MODE 0: v16   = silu(xn16 @ w_v16^T + v_b)          K=1024
// MODE 1: base  = mx16 @ w_mx16^T + mx_b (split epi)  K=1024
// MODE 2: attn16= laplace(q16 @ k16^T / L + bias)     K=128
// MODE 3: h16   = (attn16 @ vT16^T) * r               K=2048
// MODE 4: out   = x + u*(silu(hx + h16@w_h16^T+h_b)-x) K=2048
#define TM 256
#define TN 128
#define STAGE_BYTES ((TM + TN) * 64)         // 24576
#define SMEM_BYTES  (TM * 132 * 4)           // 135168 (>= 3*STAGE_BYTES)

template <int MODE>
__global__ void __launch_bounds__(256, 1)
hgemm(const float* __restrict__ bias,
      const float* __restrict__ ex0,
      const float* __restrict__ ex1,
      float* __restrict__ outp) {
    constexpr int K = (MODE == 0 || MODE == 1) ? 1024 : (MODE == 2) ? 128 : 2048;
    constexpr int NK = K / 32;
    constexpr int STAGES = 3;

    extern __shared__ char smem[];
    const uint32_t sb = smem_u32(smem);
    const int tid = threadIdx.x, lane = tid & 31, wid = tid >> 5;
    const int wm = wid & 3, wn = wid >> 2;
    const int z = blockIdx.z;
    const int rowBase = blockIdx.y * TM;
    const int colBase = blockIdx.x * TN;

    const __half* A; const __half* Bp;
    if constexpr (MODE == 0)      { A = xn16;  Bp = w_v16; }
    else if constexpr (MODE == 1) { A = mx16;  Bp = w_mx16; }
    else if constexpr (MODE == 2) { A = q16 + (size_t)z * LSEQ * ZDIM;
                                    Bp = k16 + (size_t)z * LSEQ * ZDIM; }
    else if constexpr (MODE == 3) { A = attn16 + (size_t)z * LSEQ * LSEQ;
                                    Bp = vT16 + (size_t)z * (size_t)HDIM * LSEQ; }
    else                          { A = h16;   Bp = w_h16; }

    // cp.async mapping: A 1024 16B-elems (4/thread), B 512 (2/thread)
    const int cpr = tid >> 2;        // 0..63
    const int cpc = tid & 3;         // chunk 0..3

    float acc[4][8][4];
    #pragma unroll
    for (int mi = 0; mi < 4; mi++)
        #pragma unroll
        for (int ni = 0; ni < 8; ni++)
            #pragma unroll
            for (int j = 0; j < 4; j++) acc[mi][ni][j] = 0.f;

    auto load_stage = [&](int i) {
        const int kt = i * 32;
        const uint32_t as = sb + (i % STAGES) * (uint32_t)STAGE_BYTES;
        const uint32_t bs = as + TM * 64u;
        #pragma unroll
        for (int p = 0; p < 4; p++) {
            int r = cpr + p * 64;
            CP16(as + swz(r, cpc), A + (size_t)(rowBase + r) * K + kt + cpc * 8);
        }
        #pragma unroll
        for (int p = 0; p < 2; p++) {
            int r = cpr + p * 64;
            CP16(bs + swz(r, cpc), Bp + (size_t)(colBase + r) * K + kt + cpc * 8);
        }
    };

    #pragma unroll
    for (int s = 0; s < STAGES - 1; s++) {
        if (s < NK) load_stage(s);
        CP_COMMIT();
    }

    for (int i = 0; i < NK; i++) {
        CP_WAIT(STAGES - 2);
        __syncthreads();
        const uint32_t as = sb + (i % STAGES) * (uint32_t)STAGE_BYTES;
        const uint32_t bs = as + TM * 64u;
        #pragma unroll
        for (int kk = 0; kk < 2; kk++) {
            uint32_t a[4][4], b[8][2];
            const int arow = wm * 64 + (lane & 15);
            const int achunk = kk * 2 + (lane >> 4);
            #pragma unroll
            for (int mi = 0; mi < 4; mi++)
                ldsm4(a[mi][0], a[mi][1], a[mi][2], a[mi][3],
                      as + swz(arow + mi * 16, achunk));
            const int brow = wn * 64 + (lane & 7) + ((lane >> 4) << 3);
            const int bchunk = kk * 2 + ((lane >> 3) & 1);
            #pragma unroll
            for (int nb = 0; nb < 4; nb++)
                ldsm4(b[2 * nb][0], b[2 * nb][1], b[2 * nb + 1][0], b[2 * nb + 1][1],
                      bs + swz(brow + nb * 16, bchunk));
            #pragma unroll
            for (int mi = 0; mi < 4; mi++)
                #pragma unroll
                for (int ni = 0; ni < 8; ni++)
                    mma16816(acc[mi][ni], a[mi], b[ni][0], b[ni][1]);
        }
        if (i + STAGES - 1 < NK) load_stage(i + STAGES - 1);
        CP_COMMIT();
    }
    CP_WAIT(0);
    __syncthreads();

    // phase 1: accum regs -> smem fp32 tile (pitch 132)
    float* tile = (float*)smem;
    #pragma unroll
    for (int mi = 0; mi < 4; mi++)
        #pragma unroll
        for (int ni = 0; ni < 8; ni++) {
            int r0 = wm * 64 + mi * 16 + (lane >> 2);
            int c  = wn * 64 + ni * 8 + (lane & 3) * 2;
            *(float2*)&tile[r0 * 132 + c]       = make_float2(acc[mi][ni][0], acc[mi][ni][1]);
            *(float2*)&tile[(r0 + 8) * 132 + c] = make_float2(acc[mi][ni][2], acc[mi][ni][3]);
        }
    __syncthreads();

    // phase 2: coalesced epilogue (TM*TN/4 float4 = 8192, 32 iters)
    #pragma unroll 1
    for (int p = 0; p < 32; p++) {
        int linear = p * 256 + tid;
        int rr = linear >> 5;
        int c4 = (linear & 31) * 4;
        float4 v4 = *(float4*)&tile[rr * 132 + c4];
        float vals[4] = {v4.x, v4.y, v4.z, v4.w};
        const int gr = rowBase + rr;
        const int gc0 = colBase + c4;

        if constexpr (MODE == 0) {
            int l = gr / BATCH, b = gr % BATCH;
            size_t o = ((size_t)b * LSEQ + l) * HDIM + gc0;
            __half2 p0 = __floats2half2_rn(siluf_(vals[0] + bias[gc0 + 0]),
                                           siluf_(vals[1] + bias[gc0 + 1]));
            __half2 p1 = __floats2half2_rn(siluf_(vals[2] + bias[gc0 + 2]),
                                           siluf_(vals[3] + bias[gc0 + 3]));
            *(__half2*)(v16 + o)     = p0;
            *(__half2*)(v16 + o + 2) = p1;
        } else if constexpr (MODE == 1) {
            int l = gr / BATCH, b = gr % BATCH;
            #pragma unroll
            for (int q4 = 0; q4 < 4; q4++) {
                int gc = gc0 + q4;
                float val = vals[q4] + bias[gc];
                if (gc < DDIM) {
                    g_u[(size_t)gr * DDIM + gc] = sigmoidf_(val);
                } else if (gc < DDIM + ZDIM) {
                    int zi = gc - DDIM;
                    float zz = siluf_(val);
                    size_t qo = ((size_t)b * LSEQ + l) * ZDIM + zi;
                    q16[qo] = __float2half(zz * ex0[zi]        + ex1[zi]);
                    k16[qo] = __float2half(zz * ex0[ZDIM + zi] + ex1[ZDIM + zi]);
                } else if (gc < DDIM + ZDIM + HDIM) {
                    int hi = gc - DDIM - ZDIM;
                    g_r[((size_t)b * LSEQ + l) * HDIM + hi] = siluf_(val);
                } else {
                    int di = gc - (DDIM + ZDIM + HDIM);
                    g_hx[(size_t)gr * DDIM + di] = val;
                }
            }
        } else if constexpr (MODE == 2) {
            size_t o = ((size_t)z * LSEQ + gr) * LSEQ + gc0;
            __half2 p0 = __floats2half2_rn(
                laplacef_(vals[0] * (1.f / LSEQ) + ex0[MAXPOS - 1 + gc0 + 0 - gr]),
                laplacef_(vals[1] * (1.f / LSEQ) + ex0[MAXPOS - 1 + gc0 + 1 - gr]));
            __half2 p1 = __floats2half2_rn(
                laplacef_(vals[2] * (1.f / LSEQ) + ex0[MAXPOS - 1 + gc0 + 2 - gr]),
                laplacef_(vals[3] * (1.f / LSEQ) + ex0[MAXPOS - 1 + gc0 + 3 - gr]));
            *(__half2*)(attn16 + o)     = p0;
            *(__half2*)(attn16 + o + 2) = p1;
        } else if constexpr (MODE == 3) {
            size_t o = ((size_t)z * LSEQ + gr) * HDIM + gc0;
            float4 rv = *(const float4*)(g_r + o);
            __half2 p0 = __floats2half2_rn(vals[0] * rv.x, vals[1] * rv.y);
            __half2 p1 = __floats2half2_rn(vals[2] * rv.z, vals[3] * rv.w);
            *(__half2*)(h16 + o)     = p0;
            *(__half2*)(h16 + o + 2) = p1;
        } else {  // MODE 4
            int b = gr >> 11, l = gr & (LSEQ - 1);
            size_t o = (size_t)(l * BATCH + b) * DDIM + gc0;
            float4 hx4 = *(const float4*)(g_hx + o);
            float4 u4  = *(const float4*)(g_u + o);
            float4 x4  = *(const float4*)(ex1 + o);
            float4 w4;
            w4.x = x4.x + u4.x * (siluf_(hx4.x + vals[0] + bias[gc0 + 0]) - x4.x);
            w4.y = x4.y + u4.y * (siluf_(hx4.y + vals[1] + bias[gc0 + 1]) - x4.y);
            w4.z = x4.z + u4.z * (siluf_(hx4.z + vals[2] + bias[gc0 + 2]) - x4.z);
            w4.w = x4.w + u4.w * (siluf_(hx4.w + vals[3] + bias[gc0 + 3]) - x4.w);
            *(float4*)(outp + o) = w4;
        }
    }
}

// ----------------------------------------------------------------------------
extern "C" void kernel_launch(void* const* d_in, const int* in_sizes, int n_in,
                              void* d_out, int out_size) {
    const float* x        = (const float*)d_in[0];
    const float* delta    = (const float*)d_in[1];
    const float* alpha    = (const float*)d_in[2];
    const float* beta_ema = (const float*)d_in[3];
    const float* gamma_em = (const float*)d_in[4];
    const float* omega    = (const float*)d_in[5];
    const float* v_w      = (const float*)d_in[6];
    const float* v_b      = (const float*)d_in[7];
    const float* mx_w     = (const float*)d_in[8];
    const float* mx_b     = (const float*)d_in[9];
    const float* h_w      = (const float*)d_in[10];
    const float* h_b      = (const float*)d_in[11];
    const float* qk_gamma = (const float*)d_in[12];
    const float* qk_beta  = (const float*)d_in[13];
    const float* rel_pos  = (const float*)d_in[14];
    const float* ln_w     = (const float*)d_in[15];
    const float* ln_b     = (const float*)d_in[16];
    float* out = (float*)d_out;

    cudaFuncSetAttribute(hgemm<0>, cudaFuncAttributeMaxDynamicSharedMemorySize, SMEM_BYTES);
    cudaFuncSetAttribute(hgemm<1>, cudaFuncAttributeMaxDynamicSharedMemorySize, SMEM_BYTES);
    cudaFuncSetAttribute(hgemm<2>, cudaFuncAttributeMaxDynamicSharedMemorySize, SMEM_BYTES);
    cudaFuncSetAttribute(hgemm<3>, cudaFuncAttributeMaxDynamicSharedMemorySize, SMEM_BYTES);
    cudaFuncSetAttribute(hgemm<4>, cudaFuncAttributeMaxDynamicSharedMemorySize, SMEM_BYTES);

    dim3 tblk(32, 8);

    transpose_w<0><<<dim3(HDIM / 32, DDIM / 32, 1), tblk>>>(v_w, DDIM, HDIM);
    transpose_w<1><<<dim3(DOUT / 32, DDIM / 32, 1), tblk>>>(mx_w, DDIM, DOUT);
    transpose_w<2><<<dim3(DDIM / 32, HDIM / 32, 1), tblk>>>(h_w, HDIM, DDIM);

    ln_kernel<<<LSEQ * BATCH, 256>>>(x, ln_w, ln_b);
    ema_coef_kernel<<<(DDIM * NEMA) / 256, 256>>>(delta, alpha, beta_ema, gamma_em);
    ema_scanA<<<(BATCH * DDIM * NCH) / 256, 256>>>();
    ema_scanB<<<(BATCH * DDIM) / 256, 256>>>();
    ema_scanC<<<(BATCH * DDIM * NCH) / 256, 256>>>(omega);

    // v = silu(xn @ v_w + v_b)
    hgemm<0><<<dim3(HDIM / TN, (LSEQ * BATCH) / TM, 1), 256, SMEM_BYTES>>>(
        v_b, nullptr, nullptr, nullptr);
    transpose_v16<<<dim3(HDIM / 32, LSEQ / 32, BATCH), tblk>>>();

    // base = mx @ mx_w + mx_b with split epilogue
    hgemm<1><<<dim3(DOUT / TN, (LSEQ * BATCH) / TM, 1), 256, SMEM_BYTES>>>(
        mx_b, qk_gamma, qk_beta, nullptr);

    // attn = laplace(q @ k^T / L + bias)
    hgemm<2><<<dim3(LSEQ / TN, LSEQ / TM, BATCH), 256, SMEM_BYTES>>>(
        nullptr, rel_pos, nullptr, nullptr);

    // h = (attn @ v) * r
    hgemm<3><<<dim3(HDIM / TN, LSEQ / TM, BATCH), 256, SMEM_BYTES>>>(
        nullptr, nullptr, nullptr, nullptr);

    // out = x + u * (silu(hx + h @ h_w + h_b) - x)
    hgemm<4><<<dim3(DDIM / TN, (LSEQ * BATCH) / TM, 1), 256, SMEM_BYTES>>>(
        h_b, nullptr, x, out);
}

// round 6
// speedup vs baseline: 1.0971x; 1.0971x over previous
#include <cuda_runtime.h>
#include <cuda_fp16.h>
#include <math.h>
#include <cstdint>

// ---------------------------------------------------------------------------
// MEGA forward, mma.sync fp16 GEMMs. 128x128 CTA tile (2 CTA/SM), K-chunk 64,
// 3-stage cp.async pipeline. L=2048 B=8 D=1024 Z=128 H=2048 N=16
// ---------------------------------------------------------------------------

#define LSEQ   2048
#define BATCH  8
#define DDIM   1024
#define ZDIM   128
#define HDIM   2048
#define NEMA   16
#define MAXPOS 2048
#define DOUT   (ZDIM + HDIM + 2 * DDIM)   // 4224
#define NCH    8
#define CHL    (LSEQ / NCH)               // 256

// ------------------------- scratch (device globals) ------------------------
__device__ float  g_xn  [LSEQ * BATCH * DDIM];
__device__ float  g_u   [LSEQ * BATCH * DDIM];
__device__ float  g_hx  [LSEQ * BATCH * DDIM];
__device__ float  g_r   [(size_t)BATCH * LSEQ * HDIM];
__device__ __half xn16  [LSEQ * BATCH * DDIM];
__device__ __half mx16  [LSEQ * BATCH * DDIM];
__device__ __half v16   [(size_t)BATCH * LSEQ * HDIM];
__device__ __half vT16  [(size_t)BATCH * HDIM * LSEQ];
__device__ __half h16   [(size_t)BATCH * LSEQ * HDIM];
__device__ __half q16   [BATCH * LSEQ * ZDIM];
__device__ __half k16   [BATCH * LSEQ * ZDIM];
__device__ __half attn16[(size_t)BATCH * LSEQ * LSEQ];
__device__ __half w_v16 [HDIM * DDIM];
__device__ __half w_mx16[(size_t)DOUT * DDIM];
__device__ __half w_h16 [DDIM * HDIM];
__device__ float  g_wn  [DDIM * NEMA];
__device__ float  g_qn  [DDIM * NEMA];
__device__ float  g_qp  [DDIM * NEMA];
__device__ float  g_send [BATCH * NCH * DDIM * NEMA];
__device__ float  g_carry[BATCH * NCH * DDIM * NEMA];

// ------------------------------- ptx helpers --------------------------------
__device__ __forceinline__ uint32_t smem_u32(const void* p) {
    uint32_t a;
    asm("{ .reg .u64 t; cvta.to.shared.u64 t, %1; cvt.u32.u64 %0, t; }" : "=r"(a) : "l"(p));
    return a;
}
#define CP16(dst, src) \
    asm volatile("cp.async.cg.shared.global [%0], [%1], 16;" :: "r"(dst), "l"(src))
#define CP_COMMIT() asm volatile("cp.async.commit_group;" ::: "memory")
#define CP_WAIT(n)  asm volatile("cp.async.wait_group %0;" :: "n"(n) : "memory")

__device__ __forceinline__ void ldsm4(uint32_t& r0, uint32_t& r1, uint32_t& r2,
                                      uint32_t& r3, uint32_t addr) {
    asm volatile("ldmatrix.sync.aligned.m8n8.x4.shared.b16 {%0,%1,%2,%3}, [%4];"
                 : "=r"(r0), "=r"(r1), "=r"(r2), "=r"(r3) : "r"(addr));
}
__device__ __forceinline__ void mma16816(float* d, const uint32_t* a,
                                         uint32_t b0, uint32_t b1) {
    asm volatile(
        "mma.sync.aligned.m16n8k16.row.col.f32.f16.f16.f32 "
        "{%0,%1,%2,%3}, {%4,%5,%6,%7}, {%8,%9}, {%0,%1,%2,%3};"
        : "+f"(d[0]), "+f"(d[1]), "+f"(d[2]), "+f"(d[3])
        : "r"(a[0]), "r"(a[1]), "r"(a[2]), "r"(a[3]), "r"(b0), "r"(b1));
}
// 128B rows (64 halves), 8 x 16B chunks, XOR-8 swizzle: conflict-free ldmatrix
__device__ __forceinline__ uint32_t swz(int row, int c) {
    return (uint32_t)(row * 128 + ((c ^ (row & 7)) << 4));
}

// ------------------------------- math helpers --------------------------------
__device__ __forceinline__ float sigmoidf_(float x) { return 1.f / (1.f + __expf(-x)); }
__device__ __forceinline__ float siluf_(float x)    { return x / (1.f + __expf(-x)); }
__device__ __forceinline__ float laplacef_(float x) {
    const float mu  = 0.707107f;
    const float inv = 1.0f / (0.282095f * 1.41421356237f);
    return 0.5f * (1.0f + erff((x - mu) * inv));
}

// ------------------------------ layernorm ------------------------------------
__global__ void ln_kernel(const float* __restrict__ x,
                          const float* __restrict__ w,
                          const float* __restrict__ bb) {
    int row = blockIdx.x;
    const float4* xr = (const float4*)(x + (size_t)row * DDIM);
    float4 v = xr[threadIdx.x];
    float s  = v.x + v.y + v.z + v.w;
    float s2 = v.x * v.x + v.y * v.y + v.z * v.z + v.w * v.w;
    #pragma unroll
    for (int o = 16; o; o >>= 1) {
        s  += __shfl_xor_sync(0xffffffffu, s, o);
        s2 += __shfl_xor_sync(0xffffffffu, s2, o);
    }
    __shared__ float sm[8], sm2[8];
    int wid = threadIdx.x >> 5, lid = threadIdx.x & 31;
    if (!lid) { sm[wid] = s; sm2[wid] = s2; }
    __syncthreads();
    if (threadIdx.x < 32) {
        s  = (threadIdx.x < 8) ? sm [threadIdx.x] : 0.f;
        s2 = (threadIdx.x < 8) ? sm2[threadIdx.x] : 0.f;
        #pragma unroll
        for (int o = 4; o; o >>= 1) {
            s  += __shfl_xor_sync(0xffffffffu, s, o);
            s2 += __shfl_xor_sync(0xffffffffu, s2, o);
        }
        if (!threadIdx.x) { sm[0] = s; sm2[0] = s2; }
    }
    __syncthreads();
    float mean = sm[0] * (1.f / DDIM);
    float var  = sm2[0] * (1.f / DDIM) - mean * mean;
    float rstd = rsqrtf(var + 1e-5f);
    int c = threadIdx.x * 4;
    float4 o4;
    o4.x = (v.x - mean) * rstd * w[c + 0] + bb[c + 0];
    o4.y = (v.y - mean) * rstd * w[c + 1] + bb[c + 1];
    o4.z = (v.z - mean) * rstd * w[c + 2] + bb[c + 2];
    o4.w = (v.w - mean) * rstd * w[c + 3] + bb[c + 3];
    size_t o = (size_t)row * DDIM + c;
    ((float4*)(g_xn + (size_t)row * DDIM))[threadIdx.x] = o4;
    *(__half2*)(xn16 + o)     = __floats2half2_rn(o4.x, o4.y);
    *(__half2*)(xn16 + o + 2) = __floats2half2_rn(o4.z, o4.w);
}

// --------------------------- EMA coefficients --------------------------------
__global__ void ema_coef_kernel(const float* __restrict__ delta,
                                const float* __restrict__ alpha,
                                const float* __restrict__ beta,
                                const float* __restrict__ gamma) {
    int i = blockIdx.x * 256 + threadIdx.x;
    float p = sigmoidf_(delta[i]);
    float q = 1.f - p * sigmoidf_(alpha[i]);
    g_qn[i] = q;
    g_wn[i] = p * beta[i] * gamma[i] * 0.25f;
    float qp = q;
    #pragma unroll
    for (int k = 0; k < 8; k++) qp *= qp;   // q^256
    g_qp[i] = qp;
}

// ---------------------------- EMA 3-phase scan --------------------------------
__global__ void ema_scanA() {
    int idx = blockIdx.x * 256 + threadIdx.x;
    int d = idx & (DDIM - 1);
    int t = idx >> 10;
    int b = t & 7, c = t >> 3;
    float q[NEMA], s[NEMA];
    #pragma unroll
    for (int n = 0; n < NEMA; n++) { q[n] = g_qn[d * NEMA + n]; s[n] = 0.f; }
    size_t xi = ((size_t)(c * CHL) * BATCH + b) * DDIM + d;
    for (int l = 0; l < CHL; l++) {
        float xv = g_xn[xi];
        #pragma unroll
        for (int n = 0; n < NEMA; n++) s[n] = q[n] * s[n] + xv;
        xi += (size_t)BATCH * DDIM;
    }
    float* dst = g_send + ((size_t)(b * NCH + c) * DDIM + d) * NEMA;
    #pragma unroll
    for (int n = 0; n < NEMA; n++) dst[n] = s[n];
}

__global__ void ema_scanB() {
    int idx = blockIdx.x * 256 + threadIdx.x;
    int d = idx & (DDIM - 1);
    int b = idx >> 10;
    float carry[NEMA], qp[NEMA];
    #pragma unroll
    for (int n = 0; n < NEMA; n++) { carry[n] = 0.f; qp[n] = g_qp[d * NEMA + n]; }
    for (int c = 0; c < NCH; c++) {
        float* cd = g_carry + ((size_t)(b * NCH + c) * DDIM + d) * NEMA;
        const float* sd = g_send + ((size_t)(b * NCH + c) * DDIM + d) * NEMA;
        #pragma unroll
        for (int n = 0; n < NEMA; n++) {
            cd[n] = carry[n];
            carry[n] = qp[n] * carry[n] + sd[n];
        }
    }
}

__global__ void ema_scanC(const float* __restrict__ omega) {
    int idx = blockIdx.x * 256 + threadIdx.x;
    int d = idx & (DDIM - 1);
    int t = idx >> 10;
    int b = t & 7, c = t >> 3;
    float q[NEMA], w[NEMA], s[NEMA];
    const float* cd = g_carry + ((size_t)(b * NCH + c) * DDIM + d) * NEMA;
    #pragma unroll
    for (int n = 0; n < NEMA; n++) {
        q[n] = g_qn[d * NEMA + n];
        w[n] = g_wn[d * NEMA + n];
        s[n] = cd[n];
    }
    float om = omega[d];
    size_t xi = ((size_t)(c * CHL) * BATCH + b) * DDIM + d;
    for (int l = 0; l < CHL; l++) {
        float xv = g_xn[xi];
        float a0 = 0.f, a1 = 0.f;
        #pragma unroll
        for (int n = 0; n < NEMA; n += 2) {
            s[n]     = q[n]     * s[n]     + xv;  a0 += w[n]     * s[n];
            s[n + 1] = q[n + 1] * s[n + 1] + xv;  a1 += w[n + 1] * s[n + 1];
        }
        mx16[xi] = __float2half(siluf_(a0 + a1 + om * xv));
        xi += (size_t)BATCH * DDIM;
    }
}

// ------------------------------ transposes -----------------------------------
template <int WHICH>
__global__ void transpose_w(const float* __restrict__ in, int R, int C) {
    __shared__ float t[32][33];
    __half* op = (WHICH == 0) ? w_v16 : (WHICH == 1) ? w_mx16 : w_h16;
    int c0 = blockIdx.x * 32, r0 = blockIdx.y * 32;
    int tx = threadIdx.x, ty = threadIdx.y;
    #pragma unroll
    for (int k = 0; k < 4; k++)
        t[ty + 8 * k][tx] = in[(size_t)(r0 + ty + 8 * k) * C + c0 + tx];
    __syncthreads();
    #pragma unroll
    for (int k = 0; k < 4; k++)
        op[(size_t)(c0 + ty + 8 * k) * R + r0 + tx] = __float2half(t[tx][ty + 8 * k]);
}

__global__ void transpose_v16() {
    __shared__ __half t[32][36];
    const __half* ip = v16 + (size_t)blockIdx.z * LSEQ * HDIM;
    __half* op = vT16 + (size_t)blockIdx.z * (size_t)HDIM * LSEQ;
    int c0 = blockIdx.x * 32, r0 = blockIdx.y * 32;
    int tx = threadIdx.x, ty = threadIdx.y;
    #pragma unroll
    for (int k = 0; k < 4; k++)
        t[ty + 8 * k][tx] = ip[(size_t)(r0 + ty + 8 * k) * HDIM + c0 + tx];
    __syncthreads();
    #pragma unroll
    for (int k = 0; k < 4; k++)
        op[(size_t)(c0 + ty + 8 * k) * LSEQ + r0 + tx] = t[tx][ty + 8 * k];
}

// --------------------------- fp16 mma.sync GEMM ------------------------------
// 128x128 CTA tile, 8 warps as 2(m) x 4(n), 64x32 warp tile, K-chunk 64,
// 3-stage cp.async pipeline (64 KB in flight), 2 CTAs/SM.
// MODE 0: v16   = silu(xn16 @ w_v16^T + v_b)          K=1024
// MODE 1: base  = mx16 @ w_mx16^T + mx_b (split epi)  K=1024
// MODE 2: attn16= laplace(q16 @ k16^T / L + bias)     K=128
// MODE 3: h16   = (attn16 @ vT16^T) * r               K=2048
// MODE 4: out   = x + u*(silu(hx + h16@w_h16^T+h_b)-x) K=2048
#define STAGE_BYTES 32768                 // (128+128) rows * 128 B
#define SMEM_BYTES  (3 * STAGE_BYTES)     // 98304 >= 128*132*4 epilogue tile

template <int MODE>
__global__ void __launch_bounds__(256, 2)
hgemm(const float* __restrict__ bias,
      const float* __restrict__ ex0,
      const float* __restrict__ ex1,
      float* __restrict__ outp) {
    constexpr int K = (MODE == 0 || MODE == 1) ? 1024 : (MODE == 2) ? 128 : 2048;
    constexpr int NK = K / 64;
    constexpr int STAGES = 3;

    extern __shared__ char smem[];
    const uint32_t sb = smem_u32(smem);
    const int tid = threadIdx.x, lane = tid & 31, wid = tid >> 5;
    const int wm = wid >> 2, wn = wid & 3;
    const int z = blockIdx.z;
    const int rowBase = blockIdx.y * 128;
    const int colBase = blockIdx.x * 128;

    const __half* A; const __half* Bp;
    if constexpr (MODE == 0)      { A = xn16;  Bp = w_v16; }
    else if constexpr (MODE == 1) { A = mx16;  Bp = w_mx16; }
    else if constexpr (MODE == 2) { A = q16 + (size_t)z * LSEQ * ZDIM;
                                    Bp = k16 + (size_t)z * LSEQ * ZDIM; }
    else if constexpr (MODE == 3) { A = attn16 + (size_t)z * LSEQ * LSEQ;
                                    Bp = vT16 + (size_t)z * (size_t)HDIM * LSEQ; }
    else                          { A = h16;   Bp = w_h16; }

    // cp.async: per stage A=128x8 chunks (1024), B same; 4 A + 4 B per thread
    const int cpr = tid >> 1;            // 0..127
    const int cpc = (tid & 1) * 4;       // chunk 0 or 4

    float acc[4][4][4];
    #pragma unroll
    for (int mi = 0; mi < 4; mi++)
        #pragma unroll
        for (int ni = 0; ni < 4; ni++)
            #pragma unroll
            for (int j = 0; j < 4; j++) acc[mi][ni][j] = 0.f;

    auto load_stage = [&](int i) {
        const int kt = i * 64;
        const uint32_t as = sb + (i % STAGES) * (uint32_t)STAGE_BYTES;
        const uint32_t bs = as + 16384u;
        const __half* Ar = A  + (size_t)(rowBase + cpr) * K + kt;
        const __half* Br = Bp + (size_t)(colBase + cpr) * K + kt;
        #pragma unroll
        for (int j = 0; j < 4; j++) {
            int c = cpc + j;
            CP16(as + swz(cpr, c), Ar + c * 8);
            CP16(bs + swz(cpr, c), Br + c * 8);
        }
    };

    #pragma unroll
    for (int s = 0; s < STAGES - 1; s++) {
        if (s < NK) load_stage(s);
        CP_COMMIT();
    }

    for (int i = 0; i < NK; i++) {
        CP_WAIT(STAGES - 2);
        __syncthreads();
        const uint32_t as = sb + (i % STAGES) * (uint32_t)STAGE_BYTES;
        const uint32_t bs = as + 16384u;
        #pragma unroll
        for (int kk = 0; kk < 4; kk++) {
            uint32_t a[4][4], b[4][2];
            const int arow = wm * 64 + (lane & 15);
            const int achunk = kk * 2 + (lane >> 4);
            #pragma unroll
            for (int mi = 0; mi < 4; mi++)
                ldsm4(a[mi][0], a[mi][1], a[mi][2], a[mi][3],
                      as + swz(arow + mi * 16, achunk));
            const int brow = wn * 32 + (lane & 7) + ((lane >> 4) << 3);
            const int bchunk = kk * 2 + ((lane >> 3) & 1);
            #pragma unroll
            for (int nb = 0; nb < 2; nb++)
                ldsm4(b[2 * nb][0], b[2 * nb][1], b[2 * nb + 1][0], b[2 * nb + 1][1],
                      bs + swz(brow + nb * 16, bchunk));
            #pragma unroll
            for (int mi = 0; mi < 4; mi++)
                #pragma unroll
                for (int ni = 0; ni < 4; ni++)
                    mma16816(acc[mi][ni], a[mi], b[ni][0], b[ni][1]);
        }
        if (i + STAGES - 1 < NK) load_stage(i + STAGES - 1);
        CP_COMMIT();
    }
    CP_WAIT(0);
    __syncthreads();

    // phase 1: accum regs -> smem fp32 tile (pitch 132)
    float* tile = (float*)smem;
    #pragma unroll
    for (int mi = 0; mi < 4; mi++)
        #pragma unroll
        for (int ni = 0; ni < 4; ni++) {
            int r0 = wm * 64 + mi * 16 + (lane >> 2);
            int c  = wn * 32 + ni * 8 + (lane & 3) * 2;
            *(float2*)&tile[r0 * 132 + c]       = make_float2(acc[mi][ni][0], acc[mi][ni][1]);
            *(float2*)&tile[(r0 + 8) * 132 + c] = make_float2(acc[mi][ni][2], acc[mi][ni][3]);
        }
    __syncthreads();

    // phase 2: coalesced epilogue
    #pragma unroll 1
    for (int p = 0; p < 16; p++) {
        int linear = p * 256 + tid;
        int rr = linear >> 5;
        int c4 = (linear & 31) * 4;
        float4 v4 = *(float4*)&tile[rr * 132 + c4];
        float vals[4] = {v4.x, v4.y, v4.z, v4.w};
        const int gr = rowBase + rr;
        const int gc0 = colBase + c4;

        if constexpr (MODE == 0) {
            int l = gr / BATCH, b = gr % BATCH;
            size_t o = ((size_t)b * LSEQ + l) * HDIM + gc0;
            __half2 p0 = __floats2half2_rn(siluf_(vals[0] + bias[gc0 + 0]),
                                           siluf_(vals[1] + bias[gc0 + 1]));
            __half2 p1 = __floats2half2_rn(siluf_(vals[2] + bias[gc0 + 2]),
                                           siluf_(vals[3] + bias[gc0 + 3]));
            *(__half2*)(v16 + o)     = p0;
            *(__half2*)(v16 + o + 2) = p1;
        } else if constexpr (MODE == 1) {
            int l = gr / BATCH, b = gr % BATCH;
            #pragma unroll
            for (int q4 = 0; q4 < 4; q4++) {
                int gc = gc0 + q4;
                float val = vals[q4] + bias[gc];
                if (gc < DDIM) {
                    g_u[(size_t)gr * DDIM + gc] = sigmoidf_(val);
                } else if (gc < DDIM + ZDIM) {
                    int zi = gc - DDIM;
                    float zz = siluf_(val);
                    size_t qo = ((size_t)b * LSEQ + l) * ZDIM + zi;
                    q16[qo] = __float2half(zz * ex0[zi]        + ex1[zi]);
                    k16[qo] = __float2half(zz * ex0[ZDIM + zi] + ex1[ZDIM + zi]);
                } else if (gc < DDIM + ZDIM + HDIM) {
                    int hi = gc - DDIM - ZDIM;
                    g_r[((size_t)b * LSEQ + l) * HDIM + hi] = siluf_(val);
                } else {
                    int di = gc - (DDIM + ZDIM + HDIM);
                    g_hx[(size_t)gr * DDIM + di] = val;
                }
            }
        } else if constexpr (MODE == 2) {
            size_t o = ((size_t)z * LSEQ + gr) * LSEQ + gc0;
            __half2 p0 = __floats2half2_rn(
                laplacef_(vals[0] * (1.f / LSEQ) + ex0[MAXPOS - 1 + gc0 + 0 - gr]),
                laplacef_(vals[1] * (1.f / LSEQ) + ex0[MAXPOS - 1 + gc0 + 1 - gr]));
            __half2 p1 = __floats2half2_rn(
                laplacef_(vals[2] * (1.f / LSEQ) + ex0[MAXPOS - 1 + gc0 + 2 - gr]),
                laplacef_(vals[3] * (1.f / LSEQ) + ex0[MAXPOS - 1 + gc0 + 3 - gr]));
            *(__half2*)(attn16 + o)     = p0;
            *(__half2*)(attn16 + o + 2) = p1;
        } else if constexpr (MODE == 3) {
            size_t o = ((size_t)z * LSEQ + gr) * HDIM + gc0;
            float4 rv = *(const float4*)(g_r + o);
            __half2 p0 = __floats2half2_rn(vals[0] * rv.x, vals[1] * rv.y);
            __half2 p1 = __floats2half2_rn(vals[2] * rv.z, vals[3] * rv.w);
            *(__half2*)(h16 + o)     = p0;
            *(__half2*)(h16 + o + 2) = p1;
        } else {  // MODE 4
            int b = gr >> 11, l = gr & (LSEQ - 1);
            size_t o = (size_t)(l * BATCH + b) * DDIM + gc0;
            float4 hx4 = *(const float4*)(g_hx + o);
            float4 u4  = *(const float4*)(g_u + o);
            float4 x4  = *(const float4*)(ex1 + o);
            float4 w4;
            w4.x = x4.x + u4.x * (siluf_(hx4.x + vals[0] + bias[gc0 + 0]) - x4.x);
            w4.y = x4.y + u4.y * (siluf_(hx4.y + vals[1] + bias[gc0 + 1]) - x4.y);
            w4.z = x4.z + u4.z * (siluf_(hx4.z + vals[2] + bias[gc0 + 2]) - x4.z);
            w4.w = x4.w + u4.w * (siluf_(hx4.w + vals[3] + bias[gc0 + 3]) - x4.w);
            *(float4*)(outp + o) = w4;
        }
    }
}

// ----------------------------------------------------------------------------
extern "C" void kernel_launch(void* const* d_in, const int* in_sizes, int n_in,
                              void* d_out, int out_size) {
    const float* x        = (const float*)d_in[0];
    const float* delta    = (const float*)d_in[1];
    const float* alpha    = (const float*)d_in[2];
    const float* beta_ema = (const float*)d_in[3];
    const float* gamma_em = (const float*)d_in[4];
    const float* omega    = (const float*)d_in[5];
    const float* v_w      = (const float*)d_in[6];
    const float* v_b      = (const float*)d_in[7];
    const float* mx_w     = (const float*)d_in[8];
    const float* mx_b     = (const float*)d_in[9];
    const float* h_w      = (const float*)d_in[10];
    const float* h_b      = (const float*)d_in[11];
    const float* qk_gamma = (const float*)d_in[12];
    const float* qk_beta  = (const float*)d_in[13];
    const float* rel_pos  = (const float*)d_in[14];
    const float* ln_w     = (const float*)d_in[15];
    const float* ln_b     = (const float*)d_in[16];
    float* out = (float*)d_out;

    cudaFuncSetAttribute(hgemm<0>, cudaFuncAttributeMaxDynamicSharedMemorySize, SMEM_BYTES);
    cudaFuncSetAttribute(hgemm<1>, cudaFuncAttributeMaxDynamicSharedMemorySize, SMEM_BYTES);
    cudaFuncSetAttribute(hgemm<2>, cudaFuncAttributeMaxDynamicSharedMemorySize, SMEM_BYTES);
    cudaFuncSetAttribute(hgemm<3>, cudaFuncAttributeMaxDynamicSharedMemorySize, SMEM_BYTES);
    cudaFuncSetAttribute(hgemm<4>, cudaFuncAttributeMaxDynamicSharedMemorySize, SMEM_BYTES);

    dim3 tblk(32, 8);

    transpose_w<0><<<dim3(HDIM / 32, DDIM / 32, 1), tblk>>>(v_w, DDIM, HDIM);
    transpose_w<1><<<dim3(DOUT / 32, DDIM / 32, 1), tblk>>>(mx_w, DDIM, DOUT);
    transpose_w<2><<<dim3(DDIM / 32, HDIM / 32, 1), tblk>>>(h_w, HDIM, DDIM);

    ln_kernel<<<LSEQ * BATCH, 256>>>(x, ln_w, ln_b);
    ema_coef_kernel<<<(DDIM * NEMA) / 256, 256>>>(delta, alpha, beta_ema, gamma_em);
    ema_scanA<<<(BATCH * DDIM * NCH) / 256, 256>>>();
    ema_scanB<<<(BATCH * DDIM) / 256, 256>>>();
    ema_scanC<<<(BATCH * DDIM * NCH) / 256, 256>>>(omega);

    // v = silu(xn @ v_w + v_b)
    hgemm<0><<<dim3(HDIM / 128, (LSEQ * BATCH) / 128, 1), 256, SMEM_BYTES>>>(
        v_b, nullptr, nullptr, nullptr);
    transpose_v16<<<dim3(HDIM / 32, LSEQ / 32, BATCH), tblk>>>();

    // base = mx @ mx_w + mx_b with split epilogue
    hgemm<1><<<dim3(DOUT / 128, (LSEQ * BATCH) / 128, 1), 256, SMEM_BYTES>>>(
        mx_b, qk_gamma, qk_beta, nullptr);

    // attn = laplace(q @ k^T / L + bias)
    hgemm<2><<<dim3(LSEQ / 128, LSEQ / 128, BATCH), 256, SMEM_BYTES>>>(
        nullptr, rel_pos, nullptr, nullptr);

    // h = (attn @ v) * r
    hgemm<3><<<dim3(HDIM / 128, LSEQ / 128, BATCH), 256, SMEM_BYTES>>>(
        nullptr, nullptr, nullptr, nullptr);

    // out = x + u * (silu(hx + h @ h_w + h_b) - x)
    hgemm<4><<<dim3(DDIM / 128, (LSEQ * BATCH) / 128, 1), 256, SMEM_BYTES>>>(
        h_b, nullptr, x, out);
}

// round 7
// speedup vs baseline: 1.1921x; 1.0866x over previous
#include <cuda_runtime.h>
#include <cuda_fp16.h>
#include <math.h>
#include <cstdint>

// ---------------------------------------------------------------------------
// MEGA forward, mma.sync fp16 GEMMs (round-4 mainloop, 4-stage pipeline,
// fp16 side buffers). L=2048 B=8 D=1024 Z=128 H=2048 N=16
// ---------------------------------------------------------------------------

#define LSEQ   2048
#define BATCH  8
#define DDIM   1024
#define ZDIM   128
#define HDIM   2048
#define NEMA   16
#define MAXPOS 2048
#define DOUT   (ZDIM + HDIM + 2 * DDIM)   // 4224
#define NCH    8
#define CHL    (LSEQ / NCH)               // 256

// ------------------------- scratch (device globals) ------------------------
__device__ float  g_xn  [LSEQ * BATCH * DDIM];
__device__ __half u16   [LSEQ * BATCH * DDIM];
__device__ __half hx16  [LSEQ * BATCH * DDIM];
__device__ __half r16   [(size_t)BATCH * LSEQ * HDIM];
__device__ __half xn16  [LSEQ * BATCH * DDIM];
__device__ __half mx16  [LSEQ * BATCH * DDIM];
__device__ __half v16   [(size_t)BATCH * LSEQ * HDIM];
__device__ __half vT16  [(size_t)BATCH * HDIM * LSEQ];
__device__ __half h16   [(size_t)BATCH * LSEQ * HDIM];
__device__ __half q16   [BATCH * LSEQ * ZDIM];
__device__ __half k16   [BATCH * LSEQ * ZDIM];
__device__ __half attn16[(size_t)BATCH * LSEQ * LSEQ];
__device__ __half w_v16 [HDIM * DDIM];
__device__ __half w_mx16[(size_t)DOUT * DDIM];
__device__ __half w_h16 [DDIM * HDIM];
__device__ float  g_wn  [DDIM * NEMA];
__device__ float  g_qn  [DDIM * NEMA];
__device__ float  g_qp  [DDIM * NEMA];
__device__ float  g_send [BATCH * NCH * DDIM * NEMA];
__device__ float  g_carry[BATCH * NCH * DDIM * NEMA];

// ------------------------------- ptx helpers --------------------------------
__device__ __forceinline__ uint32_t smem_u32(const void* p) {
    uint32_t a;
    asm("{ .reg .u64 t; cvta.to.shared.u64 t, %1; cvt.u32.u64 %0, t; }" : "=r"(a) : "l"(p));
    return a;
}
#define CP16(dst, src) \
    asm volatile("cp.async.cg.shared.global [%0], [%1], 16;" :: "r"(dst), "l"(src))
#define CP_COMMIT() asm volatile("cp.async.commit_group;" ::: "memory")
#define CP_WAIT(n)  asm volatile("cp.async.wait_group %0;" :: "n"(n) : "memory")

__device__ __forceinline__ void ldsm4(uint32_t& r0, uint32_t& r1, uint32_t& r2,
                                      uint32_t& r3, uint32_t addr) {
    asm volatile("ldmatrix.sync.aligned.m8n8.x4.shared.b16 {%0,%1,%2,%3}, [%4];"
                 : "=r"(r0), "=r"(r1), "=r"(r2), "=r"(r3) : "r"(addr));
}
__device__ __forceinline__ void mma16816(float* d, const uint32_t* a,
                                         uint32_t b0, uint32_t b1) {
    asm volatile(
        "mma.sync.aligned.m16n8k16.row.col.f32.f16.f16.f32 "
        "{%0,%1,%2,%3}, {%4,%5,%6,%7}, {%8,%9}, {%0,%1,%2,%3};"
        : "+f"(d[0]), "+f"(d[1]), "+f"(d[2]), "+f"(d[3])
        : "r"(a[0]), "r"(a[1]), "r"(a[2]), "r"(a[3]), "r"(b0), "r"(b1));
}
// 64B rows (32 halves), 4 x 16B chunks, XOR swizzle (round-4 validated)
__device__ __forceinline__ uint32_t swz(int row, int c) {
    return (uint32_t)(row * 64 + ((c ^ ((row >> 1) & 3)) << 4));
}

// ------------------------------- math helpers --------------------------------
__device__ __forceinline__ float sigmoidf_(float x) { return 1.f / (1.f + __expf(-x)); }
__device__ __forceinline__ float siluf_(float x)    { return x / (1.f + __expf(-x)); }
__device__ __forceinline__ float laplacef_(float x) {
    const float mu  = 0.707107f;
    const float inv = 1.0f / (0.282095f * 1.41421356237f);
    return 0.5f * (1.0f + erff((x - mu) * inv));
}

// ------------------------------ layernorm ------------------------------------
__global__ void ln_kernel(const float* __restrict__ x,
                          const float* __restrict__ w,
                          const float* __restrict__ bb) {
    int row = blockIdx.x;
    const float4* xr = (const float4*)(x + (size_t)row * DDIM);
    float4 v = xr[threadIdx.x];
    float s  = v.x + v.y + v.z + v.w;
    float s2 = v.x * v.x + v.y * v.y + v.z * v.z + v.w * v.w;
    #pragma unroll
    for (int o = 16; o; o >>= 1) {
        s  += __shfl_xor_sync(0xffffffffu, s, o);
        s2 += __shfl_xor_sync(0xffffffffu, s2, o);
    }
    __shared__ float sm[8], sm2[8];
    int wid = threadIdx.x >> 5, lid = threadIdx.x & 31;
    if (!lid) { sm[wid] = s; sm2[wid] = s2; }
    __syncthreads();
    if (threadIdx.x < 32) {
        s  = (threadIdx.x < 8) ? sm [threadIdx.x] : 0.f;
        s2 = (threadIdx.x < 8) ? sm2[threadIdx.x] : 0.f;
        #pragma unroll
        for (int o = 4; o; o >>= 1) {
            s  += __shfl_xor_sync(0xffffffffu, s, o);
            s2 += __shfl_xor_sync(0xffffffffu, s2, o);
        }
        if (!threadIdx.x) { sm[0] = s; sm2[0] = s2; }
    }
    __syncthreads();
    float mean = sm[0] * (1.f / DDIM);
    float var  = sm2[0] * (1.f / DDIM) - mean * mean;
    float rstd = rsqrtf(var + 1e-5f);
    int c = threadIdx.x * 4;
    float4 o4;
    o4.x = (v.x - mean) * rstd * w[c + 0] + bb[c + 0];
    o4.y = (v.y - mean) * rstd * w[c + 1] + bb[c + 1];
    o4.z = (v.z - mean) * rstd * w[c + 2] + bb[c + 2];
    o4.w = (v.w - mean) * rstd * w[c + 3] + bb[c + 3];
    size_t o = (size_t)row * DDIM + c;
    ((float4*)(g_xn + (size_t)row * DDIM))[threadIdx.x] = o4;
    *(__half2*)(xn16 + o)     = __floats2half2_rn(o4.x, o4.y);
    *(__half2*)(xn16 + o + 2) = __floats2half2_rn(o4.z, o4.w);
}

// --------------------------- EMA coefficients --------------------------------
__global__ void ema_coef_kernel(const float* __restrict__ delta,
                                const float* __restrict__ alpha,
                                const float* __restrict__ beta,
                                const float* __restrict__ gamma) {
    int i = blockIdx.x * 256 + threadIdx.x;
    float p = sigmoidf_(delta[i]);
    float q = 1.f - p * sigmoidf_(alpha[i]);
    g_qn[i] = q;
    g_wn[i] = p * beta[i] * gamma[i] * 0.25f;
    float qp = q;
    #pragma unroll
    for (int k = 0; k < 8; k++) qp *= qp;   // q^256
    g_qp[i] = qp;
}

// ---------------------------- EMA 3-phase scan --------------------------------
__global__ void ema_scanA() {
    int idx = blockIdx.x * 256 + threadIdx.x;
    int d = idx & (DDIM - 1);
    int t = idx >> 10;
    int b = t & 7, c = t >> 3;
    float q[NEMA], s[NEMA];
    #pragma unroll
    for (int n = 0; n < NEMA; n++) { q[n] = g_qn[d * NEMA + n]; s[n] = 0.f; }
    size_t xi = ((size_t)(c * CHL) * BATCH + b) * DDIM + d;
    for (int l = 0; l < CHL; l++) {
        float xv = g_xn[xi];
        #pragma unroll
        for (int n = 0; n < NEMA; n++) s[n] = q[n] * s[n] + xv;
        xi += (size_t)BATCH * DDIM;
    }
    float* dst = g_send + ((size_t)(b * NCH + c) * DDIM + d) * NEMA;
    #pragma unroll
    for (int n = 0; n < NEMA; n++) dst[n] = s[n];
}

__global__ void ema_scanB() {
    int idx = blockIdx.x * 256 + threadIdx.x;
    int d = idx & (DDIM - 1);
    int b = idx >> 10;
    float carry[NEMA], qp[NEMA];
    #pragma unroll
    for (int n = 0; n < NEMA; n++) { carry[n] = 0.f; qp[n] = g_qp[d * NEMA + n]; }
    for (int c = 0; c < NCH; c++) {
        float* cd = g_carry + ((size_t)(b * NCH + c) * DDIM + d) * NEMA;
        const float* sd = g_send + ((size_t)(b * NCH + c) * DDIM + d) * NEMA;
        #pragma unroll
        for (int n = 0; n < NEMA; n++) {
            cd[n] = carry[n];
            carry[n] = qp[n] * carry[n] + sd[n];
        }
    }
}

__global__ void ema_scanC(const float* __restrict__ omega) {
    int idx = blockIdx.x * 256 + threadIdx.x;
    int d = idx & (DDIM - 1);
    int t = idx >> 10;
    int b = t & 7, c = t >> 3;
    float q[NEMA], w[NEMA], s[NEMA];
    const float* cd = g_carry + ((size_t)(b * NCH + c) * DDIM + d) * NEMA;
    #pragma unroll
    for (int n = 0; n < NEMA; n++) {
        q[n] = g_qn[d * NEMA + n];
        w[n] = g_wn[d * NEMA + n];
        s[n] = cd[n];
    }
    float om = omega[d];
    size_t xi = ((size_t)(c * CHL) * BATCH + b) * DDIM + d;
    for (int l = 0; l < CHL; l++) {
        float xv = g_xn[xi];
        float a0 = 0.f, a1 = 0.f;
        #pragma unroll
        for (int n = 0; n < NEMA; n += 2) {
            s[n]     = q[n]     * s[n]     + xv;  a0 += w[n]     * s[n];
            s[n + 1] = q[n + 1] * s[n + 1] + xv;  a1 += w[n + 1] * s[n + 1];
        }
        mx16[xi] = __float2half(siluf_(a0 + a1 + om * xv));
        xi += (size_t)BATCH * DDIM;
    }
}

// ------------------------------ transposes -----------------------------------
template <int WHICH>
__global__ void transpose_w(const float* __restrict__ in, int R, int C) {
    __shared__ float t[32][33];
    __half* op = (WHICH == 0) ? w_v16 : (WHICH == 1) ? w_mx16 : w_h16;
    int c0 = blockIdx.x * 32, r0 = blockIdx.y * 32;
    int tx = threadIdx.x, ty = threadIdx.y;
    #pragma unroll
    for (int k = 0; k < 4; k++)
        t[ty + 8 * k][tx] = in[(size_t)(r0 + ty + 8 * k) * C + c0 + tx];
    __syncthreads();
    #pragma unroll
    for (int k = 0; k < 4; k++)
        op[(size_t)(c0 + ty + 8 * k) * R + r0 + tx] = __float2half(t[tx][ty + 8 * k]);
}

__global__ void transpose_v16() {
    __shared__ __half t[32][36];
    const __half* ip = v16 + (size_t)blockIdx.z * LSEQ * HDIM;
    __half* op = vT16 + (size_t)blockIdx.z * (size_t)HDIM * LSEQ;
    int c0 = blockIdx.x * 32, r0 = blockIdx.y * 32;
    int tx = threadIdx.x, ty = threadIdx.y;
    #pragma unroll
    for (int k = 0; k < 4; k++)
        t[ty + 8 * k][tx] = ip[(size_t)(r0 + ty + 8 * k) * HDIM + c0 + tx];
    __syncthreads();
    #pragma unroll
    for (int k = 0; k < 4; k++)
        op[(size_t)(c0 + ty + 8 * k) * LSEQ + r0 + tx] = t[tx][ty + 8 * k];
}

// --------------------------- fp16 mma.sync GEMM ------------------------------
// 128x128 CTA tile, 8 warps as 2(m) x 4(n), 64x32 warp tile, K-chunk 32,
// 4-stage cp.async pipeline, 2 CTAs/SM.
// MODE 0: v16   = silu(xn16 @ w_v16^T + v_b)          K=1024
// MODE 1: base  = mx16 @ w_mx16^T + mx_b (split epi)  K=1024
// MODE 2: attn16= laplace(q16 @ k16^T / L + bias)     K=128
// MODE 3: h16   = (attn16 @ vT16^T) * r               K=2048
// MODE 4: out   = x + u*(silu(hx + h16@w_h16^T+h_b)-x) K=2048
#define SMEM_BYTES (128 * 132 * 4)   // 67584; mainloop needs 4*16384=65536

template <int MODE>
__global__ void __launch_bounds__(256)
hgemm(const float* __restrict__ bias,
      const float* __restrict__ ex0,
      const float* __restrict__ ex1,
      float* __restrict__ outp) {
    constexpr int K = (MODE == 0 || MODE == 1) ? 1024 : (MODE == 2) ? 128 : 2048;
    constexpr int NK = K / 32;
    constexpr int STAGES = 4;

    extern __shared__ char smem[];
    const uint32_t sb = smem_u32(smem);
    const int tid = threadIdx.x, lane = tid & 31, wid = tid >> 5;
    const int wm = wid >> 2, wn = wid & 3;
    const int z = blockIdx.z;
    const int rowBase = blockIdx.y * 128;
    const int colBase = blockIdx.x * 128;

    const __half* A; const __half* Bp;
    if constexpr (MODE == 0)      { A = xn16;  Bp = w_v16; }
    else if constexpr (MODE == 1) { A = mx16;  Bp = w_mx16; }
    else if constexpr (MODE == 2) { A = q16 + (size_t)z * LSEQ * ZDIM;
                                    Bp = k16 + (size_t)z * LSEQ * ZDIM; }
    else if constexpr (MODE == 3) { A = attn16 + (size_t)z * LSEQ * LSEQ;
                                    Bp = vT16 + (size_t)z * (size_t)HDIM * LSEQ; }
    else                          { A = h16;   Bp = w_h16; }

    // cp.async mapping: 512 16B-elems per tile, 2 per thread
    const int e0r = tid >> 2,          e0c = tid & 3;
    const int e1r = (tid + 256) >> 2;  // e1c == e0c

    float acc[4][4][4];
    #pragma unroll
    for (int mi = 0; mi < 4; mi++)
        #pragma unroll
        for (int ni = 0; ni < 4; ni++)
            #pragma unroll
            for (int j = 0; j < 4; j++) acc[mi][ni][j] = 0.f;

    auto load_stage = [&](int i) {
        const int kt = i * 32;
        const uint32_t as = sb + (i % STAGES) * 16384u;
        const uint32_t bs = as + 8192u;
        CP16(as + swz(e0r, e0c), A  + (size_t)(rowBase + e0r) * K + kt + e0c * 8);
        CP16(as + swz(e1r, e0c), A  + (size_t)(rowBase + e1r) * K + kt + e0c * 8);
        CP16(bs + swz(e0r, e0c), Bp + (size_t)(colBase + e0r) * K + kt + e0c * 8);
        CP16(bs + swz(e1r, e0c), Bp + (size_t)(colBase + e1r) * K + kt + e0c * 8);
    };

    #pragma unroll
    for (int s = 0; s < STAGES - 1; s++) {
        if (s < NK) load_stage(s);
        CP_COMMIT();
    }

    for (int i = 0; i < NK; i++) {
        CP_WAIT(STAGES - 2);
        __syncthreads();
        const uint32_t as = sb + (i % STAGES) * 16384u;
        const uint32_t bs = as + 8192u;
        #pragma unroll
        for (int kk = 0; kk < 2; kk++) {
            uint32_t a[4][4], b[4][2];
            const int arow = wm * 64 + (lane & 15);
            const int achunk = kk * 2 + (lane >> 4);
            #pragma unroll
            for (int mi = 0; mi < 4; mi++)
                ldsm4(a[mi][0], a[mi][1], a[mi][2], a[mi][3],
                      as + swz(arow + mi * 16, achunk));
            const int brow = wn * 32 + (lane & 7) + ((lane >> 4) << 3);
            const int bchunk = kk * 2 + ((lane >> 3) & 1);
            #pragma unroll
            for (int nb = 0; nb < 2; nb++)
                ldsm4(b[2 * nb][0], b[2 * nb][1], b[2 * nb + 1][0], b[2 * nb + 1][1],
                      bs + swz(brow + nb * 16, bchunk));
            #pragma unroll
            for (int mi = 0; mi < 4; mi++)
                #pragma unroll
                for (int ni = 0; ni < 4; ni++)
                    mma16816(acc[mi][ni], a[mi], b[ni][0], b[ni][1]);
        }
        if (i + STAGES - 1 < NK) load_stage(i + STAGES - 1);
        CP_COMMIT();
    }
    CP_WAIT(0);
    __syncthreads();

    // phase 1: accum regs -> smem fp32 tile (pitch 132)
    float* tile = (float*)smem;
    #pragma unroll
    for (int mi = 0; mi < 4; mi++)
        #pragma unroll
        for (int ni = 0; ni < 4; ni++) {
            int r0 = wm * 64 + mi * 16 + (lane >> 2);
            int c  = wn * 32 + ni * 8 + (lane & 3) * 2;
            *(float2*)&tile[r0 * 132 + c]       = make_float2(acc[mi][ni][0], acc[mi][ni][1]);
            *(float2*)&tile[(r0 + 8) * 132 + c] = make_float2(acc[mi][ni][2], acc[mi][ni][3]);
        }
    __syncthreads();

    // phase 2: coalesced epilogue
    #pragma unroll 1
    for (int p = 0; p < 16; p++) {
        int linear = p * 256 + tid;
        int rr = linear >> 5;
        int c4 = (linear & 31) * 4;
        float4 v4 = *(float4*)&tile[rr * 132 + c4];
        float vals[4] = {v4.x, v4.y, v4.z, v4.w};
        const int gr = rowBase + rr;
        const int gc0 = colBase + c4;

        if constexpr (MODE == 0) {
            int l = gr / BATCH, b = gr % BATCH;
            size_t o = ((size_t)b * LSEQ + l) * HDIM + gc0;
            __half2 p0 = __floats2half2_rn(siluf_(vals[0] + bias[gc0 + 0]),
                                           siluf_(vals[1] + bias[gc0 + 1]));
            __half2 p1 = __floats2half2_rn(siluf_(vals[2] + bias[gc0 + 2]),
                                           siluf_(vals[3] + bias[gc0 + 3]));
            *(__half2*)(v16 + o)     = p0;
            *(__half2*)(v16 + o + 2) = p1;
        } else if constexpr (MODE == 1) {
            int l = gr / BATCH, b = gr % BATCH;
            float f0 = vals[0] + bias[gc0 + 0];
            float f1 = vals[1] + bias[gc0 + 1];
            float f2 = vals[2] + bias[gc0 + 2];
            float f3 = vals[3] + bias[gc0 + 3];
            // segment boundaries are multiples of 128 => a 4-group never straddles
            if (gc0 < DDIM) {
                size_t o = (size_t)gr * DDIM + gc0;
                *(__half2*)(u16 + o)     = __floats2half2_rn(sigmoidf_(f0), sigmoidf_(f1));
                *(__half2*)(u16 + o + 2) = __floats2half2_rn(sigmoidf_(f2), sigmoidf_(f3));
            } else if (gc0 < DDIM + ZDIM) {
                int zi = gc0 - DDIM;
                size_t qo = ((size_t)b * LSEQ + l) * ZDIM + zi;
                float z0 = siluf_(f0), z1 = siluf_(f1), z2 = siluf_(f2), z3 = siluf_(f3);
                *(__half2*)(q16 + qo) = __floats2half2_rn(
                    z0 * ex0[zi + 0] + ex1[zi + 0], z1 * ex0[zi + 1] + ex1[zi + 1]);
                *(__half2*)(q16 + qo + 2) = __floats2half2_rn(
                    z2 * ex0[zi + 2] + ex1[zi + 2], z3 * ex0[zi + 3] + ex1[zi + 3]);
                *(__half2*)(k16 + qo) = __floats2half2_rn(
                    z0 * ex0[ZDIM + zi + 0] + ex1[ZDIM + zi + 0],
                    z1 * ex0[ZDIM + zi + 1] + ex1[ZDIM + zi + 1]);
                *(__half2*)(k16 + qo + 2) = __floats2half2_rn(
                    z2 * ex0[ZDIM + zi + 2] + ex1[ZDIM + zi + 2],
                    z3 * ex0[ZDIM + zi + 3] + ex1[ZDIM + zi + 3]);
            } else if (gc0 < DDIM + ZDIM + HDIM) {
                int hi = gc0 - DDIM - ZDIM;
                size_t o = ((size_t)b * LSEQ + l) * HDIM + hi;
                *(__half2*)(r16 + o)     = __floats2half2_rn(siluf_(f0), siluf_(f1));
                *(__half2*)(r16 + o + 2) = __floats2half2_rn(siluf_(f2), siluf_(f3));
            } else {
                int di = gc0 - (DDIM + ZDIM + HDIM);
                size_t o = (size_t)gr * DDIM + di;
                *(__half2*)(hx16 + o)     = __floats2half2_rn(f0, f1);
                *(__half2*)(hx16 + o + 2) = __floats2half2_rn(f2, f3);
            }
        } else if constexpr (MODE == 2) {
            size_t o = ((size_t)z * LSEQ + gr) * LSEQ + gc0;
            __half2 p0 = __floats2half2_rn(
                laplacef_(vals[0] * (1.f / LSEQ) + ex0[MAXPOS - 1 + gc0 + 0 - gr]),
                laplacef_(vals[1] * (1.f / LSEQ) + ex0[MAXPOS - 1 + gc0 + 1 - gr]));
            __half2 p1 = __floats2half2_rn(
                laplacef_(vals[2] * (1.f / LSEQ) + ex0[MAXPOS - 1 + gc0 + 2 - gr]),
                laplacef_(vals[3] * (1.f / LSEQ) + ex0[MAXPOS - 1 + gc0 + 3 - gr]));
            *(__half2*)(attn16 + o)     = p0;
            *(__half2*)(attn16 + o + 2) = p1;
        } else if constexpr (MODE == 3) {
            size_t o = ((size_t)z * LSEQ + gr) * HDIM + gc0;
            float2 r0 = __half22float2(*(const __half2*)(r16 + o));
            float2 r1 = __half22float2(*(const __half2*)(r16 + o + 2));
            __half2 p0 = __floats2half2_rn(vals[0] * r0.x, vals[1] * r0.y);
            __half2 p1 = __floats2half2_rn(vals[2] * r1.x, vals[3] * r1.y);
            *(__half2*)(h16 + o)     = p0;
            *(__half2*)(h16 + o + 2) = p1;
        } else {  // MODE 4
            int b = gr >> 11, l = gr & (LSEQ - 1);
            size_t o = (size_t)(l * BATCH + b) * DDIM + gc0;
            float2 hx0 = __half22float2(*(const __half2*)(hx16 + o));
            float2 hx1 = __half22float2(*(const __half2*)(hx16 + o + 2));
            float2 uu0 = __half22float2(*(const __half2*)(u16 + o));
            float2 uu1 = __half22float2(*(const __half2*)(u16 + o + 2));
            float4 x4  = *(const float4*)(ex1 + o);
            float4 w4;
            w4.x = x4.x + uu0.x * (siluf_(hx0.x + vals[0] + bias[gc0 + 0]) - x4.x);
            w4.y = x4.y + uu0.y * (siluf_(hx0.y + vals[1] + bias[gc0 + 1]) - x4.y);
            w4.z = x4.z + uu1.x * (siluf_(hx1.x + vals[2] + bias[gc0 + 2]) - x4.z);
            w4.w = x4.w + uu1.y * (siluf_(hx1.y + vals[3] + bias[gc0 + 3]) - x4.w);
            *(float4*)(outp + o) = w4;
        }
    }
}

// ----------------------------------------------------------------------------
extern "C" void kernel_launch(void* const* d_in, const int* in_sizes, int n_in,
                              void* d_out, int out_size) {
    const float* x        = (const float*)d_in[0];
    const float* delta    = (const float*)d_in[1];
    const float* alpha    = (const float*)d_in[2];
    const float* beta_ema = (const float*)d_in[3];
    const float* gamma_em = (const float*)d_in[4];
    const float* omega    = (const float*)d_in[5];
    const float* v_w      = (const float*)d_in[6];
    const float* v_b      = (const float*)d_in[7];
    const float* mx_w     = (const float*)d_in[8];
    const float* mx_b     = (const float*)d_in[9];
    const float* h_w      = (const float*)d_in[10];
    const float* h_b      = (const float*)d_in[11];
    const float* qk_gamma = (const float*)d_in[12];
    const float* qk_beta  = (const float*)d_in[13];
    const float* rel_pos  = (const float*)d_in[14];
    const float* ln_w     = (const float*)d_in[15];
    const float* ln_b     = (const float*)d_in[16];
    float* out = (float*)d_out;

    cudaFuncSetAttribute(hgemm<0>, cudaFuncAttributeMaxDynamicSharedMemorySize, SMEM_BYTES);
    cudaFuncSetAttribute(hgemm<1>, cudaFuncAttributeMaxDynamicSharedMemorySize, SMEM_BYTES);
    cudaFuncSetAttribute(hgemm<2>, cudaFuncAttributeMaxDynamicSharedMemorySize, SMEM_BYTES);
    cudaFuncSetAttribute(hgemm<3>, cudaFuncAttributeMaxDynamicSharedMemorySize, SMEM_BYTES);
    cudaFuncSetAttribute(hgemm<4>, cudaFuncAttributeMaxDynamicSharedMemorySize, SMEM_BYTES);

    dim3 tblk(32, 8);

    transpose_w<0><<<dim3(HDIM / 32, DDIM / 32, 1), tblk>>>(v_w, DDIM, HDIM);
    transpose_w<1><<<dim3(DOUT / 32, DDIM / 32, 1), tblk>>>(mx_w, DDIM, DOUT);
    transpose_w<2><<<dim3(DDIM / 32, HDIM / 32, 1), tblk>>>(h_w, HDIM, DDIM);

    ln_kernel<<<LSEQ * BATCH, 256>>>(x, ln_w, ln_b);
    ema_coef_kernel<<<(DDIM * NEMA) / 256, 256>>>(delta, alpha, beta_ema, gamma_em);
    ema_scanA<<<(BATCH * DDIM * NCH) / 256, 256>>>();
    ema_scanB<<<(BATCH * DDIM) / 256, 256>>>();
    ema_scanC<<<(BATCH * DDIM * NCH) / 256, 256>>>(omega);

    // v = silu(xn @ v_w + v_b)
    hgemm<0><<<dim3(HDIM / 128, (LSEQ * BATCH) / 128, 1), 256, SMEM_BYTES>>>(
        v_b, nullptr, nullptr, nullptr);
    transpose_v16<<<dim3(HDIM / 32, LSEQ / 32, BATCH), tblk>>>();

    // base = mx @ mx_w + mx_b with split epilogue
    hgemm<1><<<dim3(DOUT / 128, (LSEQ * BATCH) / 128, 1), 256, SMEM_BYTES>>>(
        mx_b, qk_gamma, qk_beta, nullptr);

    // attn = laplace(q @ k^T / L + bias)
    hgemm<2><<<dim3(LSEQ / 128, LSEQ / 128, BATCH), 256, SMEM_BYTES>>>(
        nullptr, rel_pos, nullptr, nullptr);

    // h = (attn @ v) * r
    hgemm<3><<<dim3(HDIM / 128, LSEQ / 128, BATCH), 256, SMEM_BYTES>>>(
        nullptr, nullptr, nullptr, nullptr);

    // out = x + u * (silu(hx + h @ h_w + h_b) - x)
    hgemm<4><<<dim3(DDIM / 128, (LSEQ * BATCH) / 128, 1), 256, SMEM_BYTES>>>(
        h_b, nullptr, x, out);
}

// round 8
// speedup vs baseline: 1.2188x; 1.0224x over previous
#include <cuda_runtime.h>
#include <cuda_fp16.h>
#include <math.h>
#include <cstdint>

// ---------------------------------------------------------------------------
// MEGA forward, mma.sync fp16 GEMMs (128x128 tiles, 4-stage cp.async),
// fp16 everywhere off the GEMM path. L=2048 B=8 D=1024 Z=128 H=2048 N=16
// ---------------------------------------------------------------------------

#define LSEQ   2048
#define BATCH  8
#define DDIM   1024
#define ZDIM   128
#define HDIM   2048
#define NEMA   16
#define MAXPOS 2048
#define DOUT   (ZDIM + HDIM + 2 * DDIM)   // 4224
#define NCH    8
#define CHL    (LSEQ / NCH)               // 256

// ------------------------- scratch (device globals) ------------------------
__device__ __half u16   [LSEQ * BATCH * DDIM];
__device__ __half hx16  [LSEQ * BATCH * DDIM];
__device__ __half r16   [(size_t)BATCH * LSEQ * HDIM];
__device__ __half xn16  [LSEQ * BATCH * DDIM];
__device__ __half mx16  [LSEQ * BATCH * DDIM];
__device__ __half v16   [(size_t)BATCH * LSEQ * HDIM];
__device__ __half vT16  [(size_t)BATCH * HDIM * LSEQ];
__device__ __half h16   [(size_t)BATCH * LSEQ * HDIM];
__device__ __half q16   [BATCH * LSEQ * ZDIM];
__device__ __half k16   [BATCH * LSEQ * ZDIM];
__device__ __half attn16[(size_t)BATCH * LSEQ * LSEQ];
__device__ __half w_v16 [HDIM * DDIM];
__device__ __half w_mx16[(size_t)DOUT * DDIM];
__device__ __half w_h16 [DDIM * HDIM];
__device__ float  g_wn  [DDIM * NEMA];
__device__ float  g_qn  [DDIM * NEMA];
__device__ float  g_qp  [DDIM * NEMA];
__device__ float  g_send [BATCH * NCH * DDIM * NEMA];
__device__ float  g_carry[BATCH * NCH * DDIM * NEMA];

// ------------------------------- ptx helpers --------------------------------
__device__ __forceinline__ uint32_t smem_u32(const void* p) {
    uint32_t a;
    asm("{ .reg .u64 t; cvta.to.shared.u64 t, %1; cvt.u32.u64 %0, t; }" : "=r"(a) : "l"(p));
    return a;
}
#define CP16(dst, src) \
    asm volatile("cp.async.cg.shared.global [%0], [%1], 16;" :: "r"(dst), "l"(src))
#define CP_COMMIT() asm volatile("cp.async.commit_group;" ::: "memory")
#define CP_WAIT(n)  asm volatile("cp.async.wait_group %0;" :: "n"(n) : "memory")

__device__ __forceinline__ void ldsm4(uint32_t& r0, uint32_t& r1, uint32_t& r2,
                                      uint32_t& r3, uint32_t addr) {
    asm volatile("ldmatrix.sync.aligned.m8n8.x4.shared.b16 {%0,%1,%2,%3}, [%4];"
                 : "=r"(r0), "=r"(r1), "=r"(r2), "=r"(r3) : "r"(addr));
}
__device__ __forceinline__ void mma16816(float* d, const uint32_t* a,
                                         uint32_t b0, uint32_t b1) {
    asm volatile(
        "mma.sync.aligned.m16n8k16.row.col.f32.f16.f16.f32 "
        "{%0,%1,%2,%3}, {%4,%5,%6,%7}, {%8,%9}, {%0,%1,%2,%3};"
        : "+f"(d[0]), "+f"(d[1]), "+f"(d[2]), "+f"(d[3])
        : "r"(a[0]), "r"(a[1]), "r"(a[2]), "r"(a[3]), "r"(b0), "r"(b1));
}
// 64B rows (32 halves), 4 x 16B chunks, XOR swizzle (validated)
__device__ __forceinline__ uint32_t swz(int row, int c) {
    return (uint32_t)(row * 64 + ((c ^ ((row >> 1) & 3)) << 4));
}

// ------------------------------- math helpers --------------------------------
__device__ __forceinline__ float sigmoidf_(float x) { return 1.f / (1.f + __expf(-x)); }
__device__ __forceinline__ float siluf_(float x)    { return x / (1.f + __expf(-x)); }
__device__ __forceinline__ float laplacef_(float x) {
    const float mu  = 0.707107f;
    const float inv = 1.0f / (0.282095f * 1.41421356237f);
    return 0.5f * (1.0f + erff((x - mu) * inv));
}

// ------------------------------ layernorm ------------------------------------
__global__ void ln_kernel(const float* __restrict__ x,
                          const float* __restrict__ w,
                          const float* __restrict__ bb) {
    int row = blockIdx.x;
    const float4* xr = (const float4*)(x + (size_t)row * DDIM);
    float4 v = xr[threadIdx.x];
    float s  = v.x + v.y + v.z + v.w;
    float s2 = v.x * v.x + v.y * v.y + v.z * v.z + v.w * v.w;
    #pragma unroll
    for (int o = 16; o; o >>= 1) {
        s  += __shfl_xor_sync(0xffffffffu, s, o);
        s2 += __shfl_xor_sync(0xffffffffu, s2, o);
    }
    __shared__ float sm[8], sm2[8];
    int wid = threadIdx.x >> 5, lid = threadIdx.x & 31;
    if (!lid) { sm[wid] = s; sm2[wid] = s2; }
    __syncthreads();
    if (threadIdx.x < 32) {
        s  = (threadIdx.x < 8) ? sm [threadIdx.x] : 0.f;
        s2 = (threadIdx.x < 8) ? sm2[threadIdx.x] : 0.f;
        #pragma unroll
        for (int o = 4; o; o >>= 1) {
            s  += __shfl_xor_sync(0xffffffffu, s, o);
            s2 += __shfl_xor_sync(0xffffffffu, s2, o);
        }
        if (!threadIdx.x) { sm[0] = s; sm2[0] = s2; }
    }
    __syncthreads();
    float mean = sm[0] * (1.f / DDIM);
    float var  = sm2[0] * (1.f / DDIM) - mean * mean;
    float rstd = rsqrtf(var + 1e-5f);
    int c = threadIdx.x * 4;
    size_t o = (size_t)row * DDIM + c;
    *(__half2*)(xn16 + o) = __floats2half2_rn(
        (v.x - mean) * rstd * w[c + 0] + bb[c + 0],
        (v.y - mean) * rstd * w[c + 1] + bb[c + 1]);
    *(__half2*)(xn16 + o + 2) = __floats2half2_rn(
        (v.z - mean) * rstd * w[c + 2] + bb[c + 2],
        (v.w - mean) * rstd * w[c + 3] + bb[c + 3]);
}

// --------------------------- EMA coefficients --------------------------------
__global__ void ema_coef_kernel(const float* __restrict__ delta,
                                const float* __restrict__ alpha,
                                const float* __restrict__ beta,
                                const float* __restrict__ gamma) {
    int i = blockIdx.x * 256 + threadIdx.x;
    float p = sigmoidf_(delta[i]);
    float q = 1.f - p * sigmoidf_(alpha[i]);
    g_qn[i] = q;
    g_wn[i] = p * beta[i] * gamma[i] * 0.25f;
    float qp = q;
    #pragma unroll
    for (int k = 0; k < 8; k++) qp *= qp;   // q^256
    g_qp[i] = qp;
}

// ---------------------------- EMA 3-phase scan --------------------------------
__global__ void ema_scanA() {
    int idx = blockIdx.x * 256 + threadIdx.x;
    int d = idx & (DDIM - 1);
    int t = idx >> 10;
    int b = t & 7, c = t >> 3;
    float q[NEMA], s[NEMA];
    #pragma unroll
    for (int n = 0; n < NEMA; n++) { q[n] = g_qn[d * NEMA + n]; s[n] = 0.f; }
    size_t xi = ((size_t)(c * CHL) * BATCH + b) * DDIM + d;
    for (int l = 0; l < CHL; l++) {
        float xv = __half2float(xn16[xi]);
        #pragma unroll
        for (int n = 0; n < NEMA; n++) s[n] = q[n] * s[n] + xv;
        xi += (size_t)BATCH * DDIM;
    }
    float* dst = g_send + ((size_t)(b * NCH + c) * DDIM + d) * NEMA;
    #pragma unroll
    for (int n = 0; n < NEMA; n++) dst[n] = s[n];
}

__global__ void ema_scanB() {
    int idx = blockIdx.x * 256 + threadIdx.x;
    int d = idx & (DDIM - 1);
    int b = idx >> 10;
    float carry[NEMA], qp[NEMA];
    #pragma unroll
    for (int n = 0; n < NEMA; n++) { carry[n] = 0.f; qp[n] = g_qp[d * NEMA + n]; }
    for (int c = 0; c < NCH; c++) {
        float* cd = g_carry + ((size_t)(b * NCH + c) * DDIM + d) * NEMA;
        const float* sd = g_send + ((size_t)(b * NCH + c) * DDIM + d) * NEMA;
        #pragma unroll
        for (int n = 0; n < NEMA; n++) {
            cd[n] = carry[n];
            carry[n] = qp[n] * carry[n] + sd[n];
        }
    }
}

__global__ void ema_scanC(const float* __restrict__ omega) {
    int idx = blockIdx.x * 256 + threadIdx.x;
    int d = idx & (DDIM - 1);
    int t = idx >> 10;
    int b = t & 7, c = t >> 3;
    float q[NEMA], w[NEMA], s[NEMA];
    const float* cd = g_carry + ((size_t)(b * NCH + c) * DDIM + d) * NEMA;
    #pragma unroll
    for (int n = 0; n < NEMA; n++) {
        q[n] = g_qn[d * NEMA + n];
        w[n] = g_wn[d * NEMA + n];
        s[n] = cd[n];
    }
    float om = omega[d];
    size_t xi = ((size_t)(c * CHL) * BATCH + b) * DDIM + d;
    for (int l = 0; l < CHL; l++) {
        float xv = __half2float(xn16[xi]);
        float a0 = 0.f, a1 = 0.f;
        #pragma unroll
        for (int n = 0; n < NEMA; n += 2) {
            s[n]     = q[n]     * s[n]     + xv;  a0 += w[n]     * s[n];
            s[n + 1] = q[n + 1] * s[n + 1] + xv;  a1 += w[n + 1] * s[n + 1];
        }
        mx16[xi] = __float2half(siluf_(a0 + a1 + om * xv));
        xi += (size_t)BATCH * DDIM;
    }
}

// ------------------------------ transposes -----------------------------------
template <int WHICH>
__global__ void transpose_w(const float* __restrict__ in, int R, int C) {
    __shared__ float t[32][33];
    __half* op = (WHICH == 0) ? w_v16 : (WHICH == 1) ? w_mx16 : w_h16;
    int c0 = blockIdx.x * 32, r0 = blockIdx.y * 32;
    int tx = threadIdx.x, ty = threadIdx.y;
    #pragma unroll
    for (int k = 0; k < 4; k++)
        t[ty + 8 * k][tx] = in[(size_t)(r0 + ty + 8 * k) * C + c0 + tx];
    __syncthreads();
    #pragma unroll
    for (int k = 0; k < 4; k++)
        op[(size_t)(c0 + ty + 8 * k) * R + r0 + tx] = __float2half(t[tx][ty + 8 * k]);
}

// v16 (b,l,h) -> vT16 (b,h,l): 64x64 half tiles, half2 coalesced both sides
__global__ void transpose_v16() {
    __shared__ __half t[64][66];
    const __half* ip = v16 + (size_t)blockIdx.z * LSEQ * HDIM;
    __half* op = vT16 + (size_t)blockIdx.z * (size_t)HDIM * LSEQ;
    int c0 = blockIdx.x * 64, r0 = blockIdx.y * 64;
    int tx = threadIdx.x, ty = threadIdx.y;
    #pragma unroll
    for (int k = 0; k < 8; k++) {
        int r = ty + 8 * k;
        __half2 v = *(const __half2*)(ip + (size_t)(r0 + r) * HDIM + c0 + tx * 2);
        t[tx * 2 + 0][r] = __low2half(v);
        t[tx * 2 + 1][r] = __high2half(v);
    }
    __syncthreads();
    #pragma unroll
    for (int k = 0; k < 8; k++) {
        int c = ty + 8 * k;
        __half2 o = *(const __half2*)&t[c][tx * 2];
        *(__half2*)(op + (size_t)(c0 + c) * LSEQ + r0 + tx * 2) = o;
    }
}

// --------------------------- fp16 mma.sync GEMM ------------------------------
// 128x128 CTA tile, 8 warps as 2(m) x 4(n), 64x32 warp tile, K-chunk 32,
// 4-stage cp.async pipeline, 2 CTAs/SM.
// MODE 0: v16   = silu(xn16 @ w_v16^T + v_b)          K=1024
// MODE 1: base  = mx16 @ w_mx16^T + mx_b (split epi)  K=1024
// MODE 2: attn16= laplace(q16 @ k16^T / L + bias)     K=128
// MODE 3: h16   = (attn16 @ vT16^T) * r               K=2048
// MODE 4: out   = x + u*(silu(hx + h16@w_h16^T+h_b)-x) K=2048
#define SMEM_BYTES (128 * 132 * 4)   // 67584; mainloop needs 4*16384=65536

template <int MODE>
__global__ void __launch_bounds__(256)
hgemm(const float* __restrict__ bias,
      const float* __restrict__ ex0,
      const float* __restrict__ ex1,
      float* __restrict__ outp) {
    constexpr int K = (MODE == 0 || MODE == 1) ? 1024 : (MODE == 2) ? 128 : 2048;
    constexpr int NK = K / 32;
    constexpr int STAGES = 4;

    extern __shared__ char smem[];
    const uint32_t sb = smem_u32(smem);
    const int tid = threadIdx.x, lane = tid & 31, wid = tid >> 5;
    const int wm = wid >> 2, wn = wid & 3;
    const int z = blockIdx.z;
    const int rowBase = blockIdx.y * 128;
    const int colBase = blockIdx.x * 128;

    const __half* A; const __half* Bp;
    if constexpr (MODE == 0)      { A = xn16;  Bp = w_v16; }
    else if constexpr (MODE == 1) { A = mx16;  Bp = w_mx16; }
    else if constexpr (MODE == 2) { A = q16 + (size_t)z * LSEQ * ZDIM;
                                    Bp = k16 + (size_t)z * LSEQ * ZDIM; }
    else if constexpr (MODE == 3) { A = attn16 + (size_t)z * LSEQ * LSEQ;
                                    Bp = vT16 + (size_t)z * (size_t)HDIM * LSEQ; }
    else                          { A = h16;   Bp = w_h16; }

    // cp.async mapping: 512 16B-elems per tile, 2 per thread
    const int e0r = tid >> 2,          e0c = tid & 3;
    const int e1r = (tid + 256) >> 2;  // e1c == e0c

    float acc[4][4][4];
    #pragma unroll
    for (int mi = 0; mi < 4; mi++)
        #pragma unroll
        for (int ni = 0; ni < 4; ni++)
            #pragma unroll
            for (int j = 0; j < 4; j++) acc[mi][ni][j] = 0.f;

    auto load_stage = [&](int i) {
        const int kt = i * 32;
        const uint32_t as = sb + (i % STAGES) * 16384u;
        const uint32_t bs = as + 8192u;
        CP16(as + swz(e0r, e0c), A  + (size_t)(rowBase + e0r) * K + kt + e0c * 8);
        CP16(as + swz(e1r, e0c), A  + (size_t)(rowBase + e1r) * K + kt + e0c * 8);
        CP16(bs + swz(e0r, e0c), Bp + (size_t)(colBase + e0r) * K + kt + e0c * 8);
        CP16(bs + swz(e1r, e0c), Bp + (size_t)(colBase + e1r) * K + kt + e0c * 8);
    };

    #pragma unroll
    for (int s = 0; s < STAGES - 1; s++) {
        if (s < NK) load_stage(s);
        CP_COMMIT();
    }

    for (int i = 0; i < NK; i++) {
        CP_WAIT(STAGES - 2);
        __syncthreads();
        const uint32_t as = sb + (i % STAGES) * 16384u;
        const uint32_t bs = as + 8192u;
        #pragma unroll
        for (int kk = 0; kk < 2; kk++) {
            uint32_t a[4][4], b[4][2];
            const int arow = wm * 64 + (lane & 15);
            const int achunk = kk * 2 + (lane >> 4);
            #pragma unroll
            for (int mi = 0; mi < 4; mi++)
                ldsm4(a[mi][0], a[mi][1], a[mi][2], a[mi][3],
                      as + swz(arow + mi * 16, achunk));
            const int brow = wn * 32 + (lane & 7) + ((lane >> 4) << 3);
            const int bchunk = kk * 2 + ((lane >> 3) & 1);
            #pragma unroll
            for (int nb = 0; nb < 2; nb++)
                ldsm4(b[2 * nb][0], b[2 * nb][1], b[2 * nb + 1][0], b[2 * nb + 1][1],
                      bs + swz(brow + nb * 16, bchunk));
            #pragma unroll
            for (int mi = 0; mi < 4; mi++)
                #pragma unroll
                for (int ni = 0; ni < 4; ni++)
                    mma16816(acc[mi][ni], a[mi], b[ni][0], b[ni][1]);
        }
        if (i + STAGES - 1 < NK) load_stage(i + STAGES - 1);
        CP_COMMIT();
    }
    CP_WAIT(0);
    __syncthreads();

    // phase 1: accum regs -> smem fp32 tile (pitch 132)
    float* tile = (float*)smem;
    #pragma unroll
    for (int mi = 0; mi < 4; mi++)
        #pragma unroll
        for (int ni = 0; ni < 4; ni++) {
            int r0 = wm * 64 + mi * 16 + (lane >> 2);
            int c  = wn * 32 + ni * 8 + (lane & 3) * 2;
            *(float2*)&tile[r0 * 132 + c]       = make_float2(acc[mi][ni][0], acc[mi][ni][1]);
            *(float2*)&tile[(r0 + 8) * 132 + c] = make_float2(acc[mi][ni][2], acc[mi][ni][3]);
        }
    __syncthreads();

    // phase 2: coalesced epilogue
    #pragma unroll 1
    for (int p = 0; p < 16; p++) {
        int linear = p * 256 + tid;
        int rr = linear >> 5;
        int c4 = (linear & 31) * 4;
        float4 v4 = *(float4*)&tile[rr * 132 + c4];
        float vals[4] = {v4.x, v4.y, v4.z, v4.w};
        const int gr = rowBase + rr;
        const int gc0 = colBase + c4;

        if constexpr (MODE == 0) {
            int l = gr / BATCH, b = gr % BATCH;
            size_t o = ((size_t)b * LSEQ + l) * HDIM + gc0;
            __half2 p0 = __floats2half2_rn(siluf_(vals[0] + bias[gc0 + 0]),
                                           siluf_(vals[1] + bias[gc0 + 1]));
            __half2 p1 = __floats2half2_rn(siluf_(vals[2] + bias[gc0 + 2]),
                                           siluf_(vals[3] + bias[gc0 + 3]));
            *(__half2*)(v16 + o)     = p0;
            *(__half2*)(v16 + o + 2) = p1;
        } else if constexpr (MODE == 1) {
            int l = gr / BATCH, b = gr % BATCH;
            float f0 = vals[0] + bias[gc0 + 0];
            float f1 = vals[1] + bias[gc0 + 1];
            float f2 = vals[2] + bias[gc0 + 2];
            float f3 = vals[3] + bias[gc0 + 3];
            // segment boundaries are multiples of 128 => a 4-group never straddles
            if (gc0 < DDIM) {
                size_t o = (size_t)gr * DDIM + gc0;
                *(__half2*)(u16 + o)     = __floats2half2_rn(sigmoidf_(f0), sigmoidf_(f1));
                *(__half2*)(u16 + o + 2) = __floats2half2_rn(sigmoidf_(f2), sigmoidf_(f3));
            } else if (gc0 < DDIM + ZDIM) {
                int zi = gc0 - DDIM;
                size_t qo = ((size_t)b * LSEQ + l) * ZDIM + zi;
                float z0 = siluf_(f0), z1 = siluf_(f1), z2 = siluf_(f2), z3 = siluf_(f3);
                *(__half2*)(q16 + qo) = __floats2half2_rn(
                    z0 * ex0[zi + 0] + ex1[zi + 0], z1 * ex0[zi + 1] + ex1[zi + 1]);
                *(__half2*)(q16 + qo + 2) = __floats2half2_rn(
                    z2 * ex0[zi + 2] + ex1[zi + 2], z3 * ex0[zi + 3] + ex1[zi + 3]);
                *(__half2*)(k16 + qo) = __floats2half2_rn(
                    z0 * ex0[ZDIM + zi + 0] + ex1[ZDIM + zi + 0],
                    z1 * ex0[ZDIM + zi + 1] + ex1[ZDIM + zi + 1]);
                *(__half2*)(k16 + qo + 2) = __floats2half2_rn(
                    z2 * ex0[ZDIM + zi + 2] + ex1[ZDIM + zi + 2],
                    z3 * ex0[ZDIM + zi + 3] + ex1[ZDIM + zi + 3]);
            } else if (gc0 < DDIM + ZDIM + HDIM) {
                int hi = gc0 - DDIM - ZDIM;
                size_t o = ((size_t)b * LSEQ + l) * HDIM + hi;
                *(__half2*)(r16 + o)     = __floats2half2_rn(siluf_(f0), siluf_(f1));
                *(__half2*)(r16 + o + 2) = __floats2half2_rn(siluf_(f2), siluf_(f3));
            } else {
                int di = gc0 - (DDIM + ZDIM + HDIM);
                size_t o = (size_t)gr * DDIM + di;
                *(__half2*)(hx16 + o)     = __floats2half2_rn(f0, f1);
                *(__half2*)(hx16 + o + 2) = __floats2half2_rn(f2, f3);
            }
        } else if constexpr (MODE == 2) {
            size_t o = ((size_t)z * LSEQ + gr) * LSEQ + gc0;
            __half2 p0 = __floats2half2_rn(
                laplacef_(vals[0] * (1.f / LSEQ) + ex0[MAXPOS - 1 + gc0 + 0 - gr]),
                laplacef_(vals[1] * (1.f / LSEQ) + ex0[MAXPOS - 1 + gc0 + 1 - gr]));
            __half2 p1 = __floats2half2_rn(
                laplacef_(vals[2] * (1.f / LSEQ) + ex0[MAXPOS - 1 + gc0 + 2 - gr]),
                laplacef_(vals[3] * (1.f / LSEQ) + ex0[MAXPOS - 1 + gc0 + 3 - gr]));
            *(__half2*)(attn16 + o)     = p0;
            *(__half2*)(attn16 + o + 2) = p1;
        } else if constexpr (MODE == 3) {
            size_t o = ((size_t)z * LSEQ + gr) * HDIM + gc0;
            float2 r0 = __half22float2(*(const __half2*)(r16 + o));
            float2 r1 = __half22float2(*(const __half2*)(r16 + o + 2));
            __half2 p0 = __floats2half2_rn(vals[0] * r0.x, vals[1] * r0.y);
            __half2 p1 = __floats2half2_rn(vals[2] * r1.x, vals[3] * r1.y);
            *(__half2*)(h16 + o)     = p0;
            *(__half2*)(h16 + o + 2) = p1;
        } else {  // MODE 4
            int b = gr >> 11, l = gr & (LSEQ - 1);
            size_t o = (size_t)(l * BATCH + b) * DDIM + gc0;
            float2 hx0 = __half22float2(*(const __half2*)(hx16 + o));
            float2 hx1 = __half22float2(*(const __half2*)(hx16 + o + 2));
            float2 uu0 = __half22float2(*(const __half2*)(u16 + o));
            float2 uu1 = __half22float2(*(const __half2*)(u16 + o + 2));
            float4 x4  = *(const float4*)(ex1 + o);
            float4 w4;
            w4.x = x4.x + uu0.x * (siluf_(hx0.x + vals[0] + bias[gc0 + 0]) - x4.x);
            w4.y = x4.y + uu0.y * (siluf_(hx0.y + vals[1] + bias[gc0 + 1]) - x4.y);
            w4.z = x4.z + uu1.x * (siluf_(hx1.x + vals[2] + bias[gc0 + 2]) - x4.z);
            w4.w = x4.w + uu1.y * (siluf_(hx1.y + vals[3] + bias[gc0 + 3]) - x4.w);
            *(float4*)(outp + o) = w4;
        }
    }
}

// ----------------------------------------------------------------------------
extern "C" void kernel_launch(void* const* d_in, const int* in_sizes, int n_in,
                              void* d_out, int out_size) {
    const float* x        = (const float*)d_in[0];
    const float* delta    = (const float*)d_in[1];
    const float* alpha    = (const float*)d_in[2];
    const float* beta_ema = (const float*)d_in[3];
    const float* gamma_em = (const float*)d_in[4];
    const float* omega    = (const float*)d_in[5];
    const float* v_w      = (const float*)d_in[6];
    const float* v_b      = (const float*)d_in[7];
    const float* mx_w     = (const float*)d_in[8];
    const float* mx_b     = (const float*)d_in[9];
    const float* h_w      = (const float*)d_in[10];
    const float* h_b      = (const float*)d_in[11];
    const float* qk_gamma = (const float*)d_in[12];
    const float* qk_beta  = (const float*)d_in[13];
    const float* rel_pos  = (const float*)d_in[14];
    const float* ln_w     = (const float*)d_in[15];
    const float* ln_b     = (const float*)d_in[16];
    float* out = (float*)d_out;

    cudaFuncSetAttribute(hgemm<0>, cudaFuncAttributeMaxDynamicSharedMemorySize, SMEM_BYTES);
    cudaFuncSetAttribute(hgemm<1>, cudaFuncAttributeMaxDynamicSharedMemorySize, SMEM_BYTES);
    cudaFuncSetAttribute(hgemm<2>, cudaFuncAttributeMaxDynamicSharedMemorySize, SMEM_BYTES);
    cudaFuncSetAttribute(hgemm<3>, cudaFuncAttributeMaxDynamicSharedMemorySize, SMEM_BYTES);
    cudaFuncSetAttribute(hgemm<4>, cudaFuncAttributeMaxDynamicSharedMemorySize, SMEM_BYTES);

    dim3 tblk(32, 8);

    // order chosen so hgemm<0> is launch #4 (ncu -s window lands on it)
    ln_kernel<<<LSEQ * BATCH, 256>>>(x, ln_w, ln_b);
    transpose_w<0><<<dim3(HDIM / 32, DDIM / 32, 1), tblk>>>(v_w, DDIM, HDIM);
    transpose_w<2><<<dim3(DDIM / 32, HDIM / 32, 1), tblk>>>(h_w, HDIM, DDIM);

    // v = silu(xn @ v_w + v_b)
    hgemm<0><<<dim3(HDIM / 128, (LSEQ * BATCH) / 128, 1), 256, SMEM_BYTES>>>(
        v_b, nullptr, nullptr, nullptr);

    transpose_w<1><<<dim3(DOUT / 32, DDIM / 32, 1), tblk>>>(mx_w, DDIM, DOUT);
    ema_coef_kernel<<<(DDIM * NEMA) / 256, 256>>>(delta, alpha, beta_ema, gamma_em);
    ema_scanA<<<(BATCH * DDIM * NCH) / 256, 256>>>();
    ema_scanB<<<(BATCH * DDIM) / 256, 256>>>();
    ema_scanC<<<(BATCH * DDIM * NCH) / 256, 256>>>(omega);
    transpose_v16<<<dim3(HDIM / 64, LSEQ / 64, BATCH), tblk>>>();

    // base = mx @ mx_w + mx_b with split epilogue
    hgemm<1><<<dim3(DOUT / 128, (LSEQ * BATCH) / 128, 1), 256, SMEM_BYTES>>>(
        mx_b, qk_gamma, qk_beta, nullptr);

    // attn = laplace(q @ k^T / L + bias)
    hgemm<2><<<dim3(LSEQ / 128, LSEQ / 128, BATCH), 256, SMEM_BYTES>>>(
        nullptr, rel_pos, nullptr, nullptr);

    // h = (attn @ v) * r
    hgemm<3><<<dim3(HDIM / 128, LSEQ / 128, BATCH), 256, SMEM_BYTES>>>(
        nullptr, nullptr, nullptr, nullptr);

    // out = x + u * (silu(hx + h @ h_w + h_b) - x)
    hgemm<4><<<dim3(DDIM / 128, (LSEQ * BATCH) / 128, 1), 256, SMEM_BYTES>>>(
        h_b, nullptr, x, out);
}

// round 10
// speedup vs baseline: 1.4182x; 1.1637x over previous
#include <cuda_runtime.h>
#include <cuda_fp16.h>
#include <math.h>
#include <cstdint>

// ---------------------------------------------------------------------------
// MEGA forward, mma.sync fp16 GEMMs (128x128 tiles, 4-stage cp.async,
// register-double-buffered fragments). L=2048 B=8 D=1024 Z=128 H=2048 N=16
// ---------------------------------------------------------------------------

#define LSEQ   2048
#define BATCH  8
#define DDIM   1024
#define ZDIM   128
#define HDIM   2048
#define NEMA   16
#define MAXPOS 2048
#define DOUT   (ZDIM + HDIM + 2 * DDIM)   // 4224
#define NCH    8
#define CHL    (LSEQ / NCH)               // 256

// ------------------------- scratch (device globals) ------------------------
__device__ __half u16   [LSEQ * BATCH * DDIM];
__device__ __half hx16  [LSEQ * BATCH * DDIM];
__device__ __half r16   [(size_t)BATCH * LSEQ * HDIM];
__device__ __half xn16  [LSEQ * BATCH * DDIM];
__device__ __half mx16  [LSEQ * BATCH * DDIM];
__device__ __half v16   [(size_t)BATCH * LSEQ * HDIM];
__device__ __half vT16  [(size_t)BATCH * HDIM * LSEQ];
__device__ __half h16   [(size_t)BATCH * LSEQ * HDIM];
__device__ __half q16   [BATCH * LSEQ * ZDIM];
__device__ __half k16   [BATCH * LSEQ * ZDIM];
__device__ __half attn16[(size_t)BATCH * LSEQ * LSEQ];
__device__ __half w_v16 [HDIM * DDIM];
__device__ __half w_mx16[(size_t)DOUT * DDIM];
__device__ __half w_h16 [DDIM * HDIM];
__device__ float  g_wn  [DDIM * NEMA];
__device__ float  g_qn  [DDIM * NEMA];
__device__ float  g_qp  [DDIM * NEMA];
__device__ float  g_send [BATCH * NCH * DDIM * NEMA];
__device__ float  g_carry[BATCH * NCH * DDIM * NEMA];

// ------------------------------- ptx helpers --------------------------------
__device__ __forceinline__ uint32_t smem_u32(const void* p) {
    uint32_t a;
    asm("{ .reg .u64 t; cvta.to.shared.u64 t, %1; cvt.u32.u64 %0, t; }" : "=r"(a) : "l"(p));
    return a;
}
#define CP16(dst, src) \
    asm volatile("cp.async.cg.shared.global [%0], [%1], 16;" :: "r"(dst), "l"(src))
#define CP_COMMIT() asm volatile("cp.async.commit_group;" ::: "memory")
#define CP_WAIT(n)  asm volatile("cp.async.wait_group %0;" :: "n"(n) : "memory")

__device__ __forceinline__ void ldsm4(uint32_t& r0, uint32_t& r1, uint32_t& r2,
                                      uint32_t& r3, uint32_t addr) {
    asm volatile("ldmatrix.sync.aligned.m8n8.x4.shared.b16 {%0,%1,%2,%3}, [%4];"
                 : "=r"(r0), "=r"(r1), "=r"(r2), "=r"(r3) : "r"(addr));
}
__device__ __forceinline__ void mma16816(float* d, const uint32_t* a,
                                         uint32_t b0, uint32_t b1) {
    asm volatile(
        "mma.sync.aligned.m16n8k16.row.col.f32.f16.f16.f32 "
        "{%0,%1,%2,%3}, {%4,%5,%6,%7}, {%8,%9}, {%0,%1,%2,%3};"
        : "+f"(d[0]), "+f"(d[1]), "+f"(d[2]), "+f"(d[3])
        : "r"(a[0]), "r"(a[1]), "r"(a[2]), "r"(a[3]), "r"(b0), "r"(b1));
}
// 64B rows (32 halves), 4 x 16B chunks, XOR swizzle (validated)
__device__ __forceinline__ uint32_t swz(int row, int c) {
    return (uint32_t)(row * 64 + ((c ^ ((row >> 1) & 3)) << 4));
}

// ------------------------------- math helpers --------------------------------
__device__ __forceinline__ float sigmoidf_(float x) { return 1.f / (1.f + __expf(-x)); }
__device__ __forceinline__ float siluf_(float x)    { return x / (1.f + __expf(-x)); }
__device__ __forceinline__ float laplacef_(float x) {
    const float mu  = 0.707107f;
    const float inv = 1.0f / (0.282095f * 1.41421356237f);
    return 0.5f * (1.0f + erff((x - mu) * inv));
}

// ------------------------------ layernorm ------------------------------------
__global__ void ln_kernel(const float* __restrict__ x,
                          const float* __restrict__ w,
                          const float* __restrict__ bb) {
    int row = blockIdx.x;
    const float4* xr = (const float4*)(x + (size_t)row * DDIM);
    float4 v = xr[threadIdx.x];
    float s  = v.x + v.y + v.z + v.w;
    float s2 = v.x * v.x + v.y * v.y + v.z * v.z + v.w * v.w;
    #pragma unroll
    for (int o = 16; o; o >>= 1) {
        s  += __shfl_xor_sync(0xffffffffu, s, o);
        s2 += __shfl_xor_sync(0xffffffffu, s2, o);
    }
    __shared__ float sm[8], sm2[8];
    int wid = threadIdx.x >> 5, lid = threadIdx.x & 31;
    if (!lid) { sm[wid] = s; sm2[wid] = s2; }
    __syncthreads();
    if (threadIdx.x < 32) {
        s  = (threadIdx.x < 8) ? sm [threadIdx.x] : 0.f;
        s2 = (threadIdx.x < 8) ? sm2[threadIdx.x] : 0.f;
        #pragma unroll
        for (int o = 4; o; o >>= 1) {
            s  += __shfl_xor_sync(0xffffffffu, s, o);
            s2 += __shfl_xor_sync(0xffffffffu, s2, o);
        }
        if (!threadIdx.x) { sm[0] = s; sm2[0] = s2; }
    }
    __syncthreads();
    float mean = sm[0] * (1.f / DDIM);
    float var  = sm2[0] * (1.f / DDIM) - mean * mean;
    float rstd = rsqrtf(var + 1e-5f);
    int c = threadIdx.x * 4;
    size_t o = (size_t)row * DDIM + c;
    *(__half2*)(xn16 + o) = __floats2half2_rn(
        (v.x - mean) * rstd * w[c + 0] + bb[c + 0],
        (v.y - mean) * rstd * w[c + 1] + bb[c + 1]);
    *(__half2*)(xn16 + o + 2) = __floats2half2_rn(
        (v.z - mean) * rstd * w[c + 2] + bb[c + 2],
        (v.w - mean) * rstd * w[c + 3] + bb[c + 3]);
}

// --------------------------- EMA coefficients --------------------------------
__global__ void ema_coef_kernel(const float* __restrict__ delta,
                                const float* __restrict__ alpha,
                                const float* __restrict__ beta,
                                const float* __restrict__ gamma) {
    int i = blockIdx.x * 256 + threadIdx.x;
    float p = sigmoidf_(delta[i]);
    float q = 1.f - p * sigmoidf_(alpha[i]);
    g_qn[i] = q;
    g_wn[i] = p * beta[i] * gamma[i] * 0.25f;
    float qp = q;
    #pragma unroll
    for (int k = 0; k < 8; k++) qp *= qp;   // q^256
    g_qp[i] = qp;
}

// ---------------------------- EMA 3-phase scan --------------------------------
__global__ void ema_scanA() {
    int idx = blockIdx.x * 256 + threadIdx.x;
    int d = idx & (DDIM - 1);
    int t = idx >> 10;
    int b = t & 7, c = t >> 3;
    float q[NEMA], s[NEMA];
    #pragma unroll
    for (int n = 0; n < NEMA; n++) { q[n] = g_qn[d * NEMA + n]; s[n] = 0.f; }
    size_t xi = ((size_t)(c * CHL) * BATCH + b) * DDIM + d;
    for (int l = 0; l < CHL; l++) {
        float xv = __half2float(xn16[xi]);
        #pragma unroll
        for (int n = 0; n < NEMA; n++) s[n] = q[n] * s[n] + xv;
        xi += (size_t)BATCH * DDIM;
    }
    float* dst = g_send + ((size_t)(b * NCH + c) * DDIM + d) * NEMA;
    #pragma unroll
    for (int n = 0; n < NEMA; n++) dst[n] = s[n];
}

__global__ void ema_scanB() {
    int idx = blockIdx.x * 256 + threadIdx.x;
    int d = idx & (DDIM - 1);
    int b = idx >> 10;
    float carry[NEMA], qp[NEMA];
    #pragma unroll
    for (int n = 0; n < NEMA; n++) { carry[n] = 0.f; qp[n] = g_qp[d * NEMA + n]; }
    for (int c = 0; c < NCH; c++) {
        float* cd = g_carry + ((size_t)(b * NCH + c) * DDIM + d) * NEMA;
        const float* sd = g_send + ((size_t)(b * NCH + c) * DDIM + d) * NEMA;
        #pragma unroll
        for (int n = 0; n < NEMA; n++) {
            cd[n] = carry[n];
            carry[n] = qp[n] * carry[n] + sd[n];
        }
    }
}

__global__ void ema_scanC(const float* __restrict__ omega) {
    int idx = blockIdx.x * 256 + threadIdx.x;
    int d = idx & (DDIM - 1);
    int t = idx >> 10;
    int b = t & 7, c = t >> 3;
    float q[NEMA], w[NEMA], s[NEMA];
    const float* cd = g_carry + ((size_t)(b * NCH + c) * DDIM + d) * NEMA;
    #pragma unroll
    for (int n = 0; n < NEMA; n++) {
        q[n] = g_qn[d * NEMA + n];
        w[n] = g_wn[d * NEMA + n];
        s[n] = cd[n];
    }
    float om = omega[d];
    size_t xi = ((size_t)(c * CHL) * BATCH + b) * DDIM + d;
    for (int l = 0; l < CHL; l++) {
        float xv = __half2float(xn16[xi]);
        float a0 = 0.f, a1 = 0.f;
        #pragma unroll
        for (int n = 0; n < NEMA; n += 2) {
            s[n]     = q[n]     * s[n]     + xv;  a0 += w[n]     * s[n];
            s[n + 1] = q[n + 1] * s[n + 1] + xv;  a1 += w[n + 1] * s[n + 1];
        }
        mx16[xi] = __float2half(siluf_(a0 + a1 + om * xv));
        xi += (size_t)BATCH * DDIM;
    }
}

// ------------------------------ transposes -----------------------------------
template <int WHICH>
__global__ void transpose_w(const float* __restrict__ in, int R, int C) {
    __shared__ float t[32][33];
    __half* op = (WHICH == 0) ? w_v16 : (WHICH == 1) ? w_mx16 : w_h16;
    int c0 = blockIdx.x * 32, r0 = blockIdx.y * 32;
    int tx = threadIdx.x, ty = threadIdx.y;
    #pragma unroll
    for (int k = 0; k < 4; k++)
        t[ty + 8 * k][tx] = in[(size_t)(r0 + ty + 8 * k) * C + c0 + tx];
    __syncthreads();
    #pragma unroll
    for (int k = 0; k < 4; k++)
        op[(size_t)(c0 + ty + 8 * k) * R + r0 + tx] = __float2half(t[tx][ty + 8 * k]);
}

// v16 (b,l,h) -> vT16 (b,h,l): 64x64 half tiles, half2 coalesced both sides
__global__ void transpose_v16() {
    __shared__ __half t[64][66];
    const __half* ip = v16 + (size_t)blockIdx.z * LSEQ * HDIM;
    __half* op = vT16 + (size_t)blockIdx.z * (size_t)HDIM * LSEQ;
    int c0 = blockIdx.x * 64, r0 = blockIdx.y * 64;
    int tx = threadIdx.x, ty = threadIdx.y;
    #pragma unroll
    for (int k = 0; k < 8; k++) {
        int r = ty + 8 * k;
        __half2 v = *(const __half2*)(ip + (size_t)(r0 + r) * HDIM + c0 + tx * 2);
        t[tx * 2 + 0][r] = __low2half(v);
        t[tx * 2 + 1][r] = __high2half(v);
    }
    __syncthreads();
    #pragma unroll
    for (int k = 0; k < 8; k++) {
        int c = ty + 8 * k;
        __half2 o = *(const __half2*)&t[c][tx * 2];
        *(__half2*)(op + (size_t)(c0 + c) * LSEQ + r0 + tx * 2) = o;
    }
}

// --------------------------- fp16 mma.sync GEMM ------------------------------
// 128x128 CTA tile, 8 warps as 2(m) x 4(n), 64x32 warp tile, K-chunk 32,
// 4-stage cp.async pipeline, register-double-buffered frags, 2 CTAs/SM.
// MODE 0: v16   = silu(xn16 @ w_v16^T + v_b)          K=1024
// MODE 1: base  = mx16 @ w_mx16^T + mx_b (split epi)  K=1024
// MODE 2: attn16= laplace(q16 @ k16^T / L + bias)     K=128
// MODE 3: h16   = (attn16 @ vT16^T) * r               K=2048
// MODE 4: out   = x + u*(silu(hx + h16@w_h16^T+h_b)-x) K=2048
#define SMEM_BYTES (128 * 132 * 4)   // 67584; mainloop needs 4*16384=65536

template <int MODE>
__global__ void __launch_bounds__(256, 2)
hgemm(const float* __restrict__ bias,
      const float* __restrict__ ex0,
      const float* __restrict__ ex1,
      float* __restrict__ outp) {
    constexpr int K = (MODE == 0 || MODE == 1) ? 1024 : (MODE == 2) ? 128 : 2048;
    constexpr int NK = K / 32;
    constexpr int STAGES = 4;

    extern __shared__ char smem[];
    const uint32_t sb = smem_u32(smem);
    const int tid = threadIdx.x, lane = tid & 31, wid = tid >> 5;
    const int wm = wid >> 2, wn = wid & 3;
    const int z = blockIdx.z;
    const int rowBase = blockIdx.y * 128;
    const int colBase = blockIdx.x * 128;

    const __half* A; const __half* Bp;
    if constexpr (MODE == 0)      { A = xn16;  Bp = w_v16; }
    else if constexpr (MODE == 1) { A = mx16;  Bp = w_mx16; }
    else if constexpr (MODE == 2) { A = q16 + (size_t)z * LSEQ * ZDIM;
                                    Bp = k16 + (size_t)z * LSEQ * ZDIM; }
    else if constexpr (MODE == 3) { A = attn16 + (size_t)z * LSEQ * LSEQ;
                                    Bp = vT16 + (size_t)z * (size_t)HDIM * LSEQ; }
    else                          { A = h16;   Bp = w_h16; }

    // cp.async mapping: 512 16B-elems per tile, 2 per thread
    const int e0r = tid >> 2,          e0c = tid & 3;
    const int e1r = (tid + 256) >> 2;  // e1c == e0c

    float acc[4][4][4];
    #pragma unroll
    for (int mi = 0; mi < 4; mi++)
        #pragma unroll
        for (int ni = 0; ni < 4; ni++)
            #pragma unroll
            for (int j = 0; j < 4; j++) acc[mi][ni][j] = 0.f;

    auto load_stage = [&](int i) {
        const int kt = i * 32;
        const uint32_t as = sb + (i % STAGES) * 16384u;
        const uint32_t bs = as + 8192u;
        CP16(as + swz(e0r, e0c), A  + (size_t)(rowBase + e0r) * K + kt + e0c * 8);
        CP16(as + swz(e1r, e0c), A  + (size_t)(rowBase + e1r) * K + kt + e0c * 8);
        CP16(bs + swz(e0r, e0c), Bp + (size_t)(colBase + e0r) * K + kt + e0c * 8);
        CP16(bs + swz(e1r, e0c), Bp + (size_t)(colBase + e1r) * K + kt + e0c * 8);
    };

    // register-double-buffered fragments
    uint32_t afr[2][4][4], bfr[2][4][2];
    auto load_frags = [&](uint32_t as, uint32_t bs, int kk, int bf) {
        const int arow = wm * 64 + (lane & 15);
        const int achunk = kk * 2 + (lane >> 4);
        #pragma unroll
        for (int mi = 0; mi < 4; mi++)
            ldsm4(afr[bf][mi][0], afr[bf][mi][1], afr[bf][mi][2], afr[bf][mi][3],
                  as + swz(arow + mi * 16, achunk));
        const int brow = wn * 32 + (lane & 7) + ((lane >> 4) << 3);
        const int bchunk = kk * 2 + ((lane >> 3) & 1);
        #pragma unroll
        for (int nb = 0; nb < 2; nb++)
            ldsm4(bfr[bf][2 * nb][0], bfr[bf][2 * nb][1],
                  bfr[bf][2 * nb + 1][0], bfr[bf][2 * nb + 1][1],
                  bs + swz(brow + nb * 16, bchunk));
    };

    #pragma unroll
    for (int s = 0; s < STAGES - 1; s++) {
        if (s < NK) load_stage(s);
        CP_COMMIT();
    }

    for (int i = 0; i < NK; i++) {
        CP_WAIT(STAGES - 2);
        __syncthreads();
        const uint32_t as = sb + (i % STAGES) * 16384u;
        const uint32_t bs = as + 8192u;
        // issue both frag loads + next gmem stage before any MMA
        load_frags(as, bs, 0, 0);
        if (i + STAGES - 1 < NK) load_stage(i + STAGES - 1);
        CP_COMMIT();
        load_frags(as, bs, 1, 1);
        #pragma unroll
        for (int kk = 0; kk < 2; kk++)
            #pragma unroll
            for (int mi = 0; mi < 4; mi++)
                #pragma unroll
                for (int ni = 0; ni < 4; ni++)
                    mma16816(acc[mi][ni], afr[kk][mi], bfr[kk][ni][0], bfr[kk][ni][1]);
    }
    CP_WAIT(0);
    __syncthreads();

    // phase 1: accum regs -> smem fp32 tile (pitch 132)
    float* tile = (float*)smem;
    #pragma unroll
    for (int mi = 0; mi < 4; mi++)
        #pragma unroll
        for (int ni = 0; ni < 4; ni++) {
            int r0 = wm * 64 + mi * 16 + (lane >> 2);
            int c  = wn * 32 + ni * 8 + (lane & 3) * 2;
            *(float2*)&tile[r0 * 132 + c]       = make_float2(acc[mi][ni][0], acc[mi][ni][1]);
            *(float2*)&tile[(r0 + 8) * 132 + c] = make_float2(acc[mi][ni][2], acc[mi][ni][3]);
        }
    __syncthreads();

    // phase 2: coalesced epilogue
    #pragma unroll 1
    for (int p = 0; p < 16; p++) {
        int linear = p * 256 + tid;
        int rr = linear >> 5;
        int c4 = (linear & 31) * 4;
        float4 v4 = *(float4*)&tile[rr * 132 + c4];
        float vals[4] = {v4.x, v4.y, v4.z, v4.w};
        const int gr = rowBase + rr;
        const int gc0 = colBase + c4;

        if constexpr (MODE == 0) {
            int l = gr / BATCH, b = gr % BATCH;
            size_t o = ((size_t)b * LSEQ + l) * HDIM + gc0;
            __half2 p0 = __floats2half2_rn(siluf_(vals[0] + bias[gc0 + 0]),
                                           siluf_(vals[1] + bias[gc0 + 1]));
            __half2 p1 = __floats2half2_rn(siluf_(vals[2] + bias[gc0 + 2]),
                                           siluf_(vals[3] + bias[gc0 + 3]));
            *(__half2*)(v16 + o)     = p0;
            *(__half2*)(v16 + o + 2) = p1;
        } else if constexpr (MODE == 1) {
            int l = gr / BATCH, b = gr % BATCH;
            float f0 = vals[0] + bias[gc0 + 0];
            float f1 = vals[1] + bias[gc0 + 1];
            float f2 = vals[2] + bias[gc0 + 2];
            float f3 = vals[3] + bias[gc0 + 3];
            // segment boundaries are multiples of 128 => a 4-group never straddles
            if (gc0 < DDIM) {
                size_t o = (size_t)gr * DDIM + gc0;
                *(__half2*)(u16 + o)     = __floats2half2_rn(sigmoidf_(f0), sigmoidf_(f1));
                *(__half2*)(u16 + o + 2) = __floats2half2_rn(sigmoidf_(f2), sigmoidf_(f3));
            } else if (gc0 < DDIM + ZDIM) {
                int zi = gc0 - DDIM;
                size_t qo = ((size_t)b * LSEQ + l) * ZDIM + zi;
                float z0 = siluf_(f0), z1 = siluf_(f1), z2 = siluf_(f2), z3 = siluf_(f3);
                *(__half2*)(q16 + qo) = __floats2half2_rn(
                    z0 * ex0[zi + 0] + ex1[zi + 0], z1 * ex0[zi + 1] + ex1[zi + 1]);
                *(__half2*)(q16 + qo + 2) = __floats2half2_rn(
                    z2 * ex0[zi + 2] + ex1[zi + 2], z3 * ex0[zi + 3] + ex1[zi + 3]);
                *(__half2*)(k16 + qo) = __floats2half2_rn(
                    z0 * ex0[ZDIM + zi + 0] + ex1[ZDIM + zi + 0],
                    z1 * ex0[ZDIM + zi + 1] + ex1[ZDIM + zi + 1]);
                *(__half2*)(k16 + qo + 2) = __floats2half2_rn(
                    z2 * ex0[ZDIM + zi + 2] + ex1[ZDIM + zi + 2],
                    z3 * ex0[ZDIM + zi + 3] + ex1[ZDIM + zi + 3]);
            } else if (gc0 < DDIM + ZDIM + HDIM) {
                int hi = gc0 - DDIM - ZDIM;
                size_t o = ((size_t)b * LSEQ + l) * HDIM + hi;
                *(__half2*)(r16 + o)     = __floats2half2_rn(siluf_(f0), siluf_(f1));
                *(__half2*)(r16 + o + 2) = __floats2half2_rn(siluf_(f2), siluf_(f3));
            } else {
                int di = gc0 - (DDIM + ZDIM + HDIM);
                size_t o = (size_t)gr * DDIM + di;
                *(__half2*)(hx16 + o)     = __floats2half2_rn(f0, f1);
                *(__half2*)(hx16 + o + 2) = __floats2half2_rn(f2, f3);
            }
        } else if constexpr (MODE == 2) {
            size_t o = ((size_t)z * LSEQ + gr) * LSEQ + gc0;
            __half2 p0 = __floats2half2_rn(
                laplacef_(vals[0] * (1.f / LSEQ) + ex0[MAXPOS - 1 + gc0 + 0 - gr]),
                laplacef_(vals[1] * (1.f / LSEQ) + ex0[MAXPOS - 1 + gc0 + 1 - gr]));
            __half2 p1 = __floats2half2_rn(
                laplacef_(vals[2] * (1.f / LSEQ) + ex0[MAXPOS - 1 + gc0 + 2 - gr]),
                laplacef_(vals[3] * (1.f / LSEQ) + ex0[MAXPOS - 1 + gc0 + 3 - gr]));
            *(__half2*)(attn16 + o)     = p0;
            *(__half2*)(attn16 + o + 2) = p1;
        } else if constexpr (MODE == 3) {
            size_t o = ((size_t)z * LSEQ + gr) * HDIM + gc0;
            float2 r0 = __half22float2(*(const __half2*)(r16 + o));
            float2 r1 = __half22float2(*(const __half2*)(r16 + o + 2));
            __half2 p0 = __floats2half2_rn(vals[0] * r0.x, vals[1] * r0.y);
            __half2 p1 = __floats2half2_rn(vals[2] * r1.x, vals[3] * r1.y);
            *(__half2*)(h16 + o)     = p0;
            *(__half2*)(h16 + o + 2) = p1;
        } else {  // MODE 4
            int b = gr >> 11, l = gr & (LSEQ - 1);
            size_t o = (size_t)(l * BATCH + b) * DDIM + gc0;
            float2 hx0 = __half22float2(*(const __half2*)(hx16 + o));
            float2 hx1 = __half22float2(*(const __half2*)(hx16 + o + 2));
            float2 uu0 = __half22float2(*(const __half2*)(u16 + o));
            float2 uu1 = __half22float2(*(const __half2*)(u16 + o + 2));
            float4 x4  = *(const float4*)(ex1 + o);
            float4 w4;
            w4.x = x4.x + uu0.x * (siluf_(hx0.x + vals[0] + bias[gc0 + 0]) - x4.x);
            w4.y = x4.y + uu0.y * (siluf_(hx0.y + vals[1] + bias[gc0 + 1]) - x4.y);
            w4.z = x4.z + uu1.x * (siluf_(hx1.x + vals[2] + bias[gc0 + 2]) - x4.z);
            w4.w = x4.w + uu1.y * (siluf_(hx1.y + vals[3] + bias[gc0 + 3]) - x4.w);
            *(float4*)(outp + o) = w4;
        }
    }
}

// ----------------------------------------------------------------------------
extern "C" void kernel_launch(void* const* d_in, const int* in_sizes, int n_in,
                              void* d_out, int out_size) {
    const float* x        = (const float*)d_in[0];
    const float* delta    = (const float*)d_in[1];
    const float* alpha    = (const float*)d_in[2];
    const float* beta_ema = (const float*)d_in[3];
    const float* gamma_em = (const float*)d_in[4];
    const float* omega    = (const float*)d_in[5];
    const float* v_w      = (const float*)d_in[6];
    const float* v_b      = (const float*)d_in[7];
    const float* mx_w     = (const float*)d_in[8];
    const float* mx_b     = (const float*)d_in[9];
    const float* h_w      = (const float*)d_in[10];
    const float* h_b      = (const float*)d_in[11];
    const float* qk_gamma = (const float*)d_in[12];
    const float* qk_beta  = (const float*)d_in[13];
    const float* rel_pos  = (const float*)d_in[14];
    const float* ln_w     = (const float*)d_in[15];
    const float* ln_b     = (const float*)d_in[16];
    float* out = (float*)d_out;

    cudaFuncSetAttribute(hgemm<0>, cudaFuncAttributeMaxDynamicSharedMemorySize, SMEM_BYTES);
    cudaFuncSetAttribute(hgemm<1>, cudaFuncAttributeMaxDynamicSharedMemorySize, SMEM_BYTES);
    cudaFuncSetAttribute(hgemm<2>, cudaFuncAttributeMaxDynamicSharedMemorySize, SMEM_BYTES);
    cudaFuncSetAttribute(hgemm<3>, cudaFuncAttributeMaxDynamicSharedMemorySize, SMEM_BYTES);
    cudaFuncSetAttribute(hgemm<4>, cudaFuncAttributeMaxDynamicSharedMemorySize, SMEM_BYTES);

    dim3 tblk(32, 8);

    // order chosen so hgemm<0> is launch #4 (ncu -s window lands on it)
    ln_kernel<<<LSEQ * BATCH, 256>>>(x, ln_w, ln_b);
    transpose_w<0><<<dim3(HDIM / 32, DDIM / 32, 1), tblk>>>(v_w, DDIM, HDIM);
    transpose_w<2><<<dim3(DDIM / 32, HDIM / 32, 1), tblk>>>(h_w, HDIM, DDIM);

    // v = silu(xn @ v_w + v_b)
    hgemm<0><<<dim3(HDIM / 128, (LSEQ * BATCH) / 128, 1), 256, SMEM_BYTES>>>(
        v_b, nullptr, nullptr, nullptr);

    transpose_w<1><<<dim3(DOUT / 32, DDIM / 32, 1), tblk>>>(mx_w, DDIM, DOUT);
    ema_coef_kernel<<<(DDIM * NEMA) / 256, 256>>>(delta, alpha, beta_ema, gamma_em);
    ema_scanA<<<(BATCH * DDIM * NCH) / 256, 256>>>();
    ema_scanB<<<(BATCH * DDIM) / 256, 256>>>();
    ema_scanC<<<(BATCH * DDIM * NCH) / 256, 256>>>(omega);
    transpose_v16<<<dim3(HDIM / 64, LSEQ / 64, BATCH), tblk>>>();

    // base = mx @ mx_w + mx_b with split epilogue
    hgemm<1><<<dim3(DOUT / 128, (LSEQ * BATCH) / 128, 1), 256, SMEM_BYTES>>>(
        mx_b, qk_gamma, qk_beta, nullptr);

    // attn = laplace(q @ k^T / L + bias)
    hgemm<2><<<dim3(LSEQ / 128, LSEQ / 128, BATCH), 256, SMEM_BYTES>>>(
        nullptr, rel_pos, nullptr, nullptr);

    // h = (attn @ v) * r
    hgemm<3><<<dim3(HDIM / 128, LSEQ / 128, BATCH), 256, SMEM_BYTES>>>(
        nullptr, nullptr, nullptr, nullptr);

    // out = x + u * (silu(hx + h @ h_w + h_b) - x)
    hgemm<4><<<dim3(DDIM / 128, (LSEQ * BATCH) / 128, 1), 256, SMEM_BYTES>>>(
        h_b, nullptr, x, out);
}